// round 10
// baseline (speedup 1.0000x reference)
#include <cuda_runtime.h>
#include <math.h>

// Problem constants (shapes fixed by dataset)
#define NMAX 50000
#define EMAX 800000
#define GNUM 64
// F=64, HG=HL=128; virtual feat width = 64 + 12*64 = 832

// ---------------- scratch (__device__ globals; no allocation allowed) ----------
__device__ float    d_pq[NMAX * 128];          // [p | q] per node
__device__ int      d_deg[NMAX];
__device__ int      d_off[NMAX];
__device__ int      d_fill[NMAX];
__device__ int      d_srcS[EMAX];              // src reordered by dst-CSR position
__device__ float    d_eaS[EMAX];               // edge_attr reordered likewise
__device__ float    d_agg[(size_t)NMAX * 256]; // [mean|mn|mx|sd] per node
__device__ float    d_amp[NMAX];
__device__ float    d_iamp[NMAX];
__device__ float    d_h[NMAX * 128];
__device__ float    d_Wds[64 * 128];           // [Wd | Ws]
__device__ float    d_Wc[832 * 128];           // W_post @ W_lin
__device__ float    d_bc[128];                 // b_post @ W_lin + b_lin
__device__ float    d_v[64];                   // W_edge @ W_pre_e
__device__ float    d_cvec[64];                // b_edge @ W_pre_e + b_pre
__device__ float    d_zsum[GNUM * 128];
__device__ float    d_gcnt[GNUM];

// ------------------------- f32x2 packed helpers --------------------------------
__device__ __forceinline__ unsigned long long dup2(float x) {
    unsigned long long r;
    asm("mov.b64 %0, {%1, %1};" : "=l"(r) : "f"(x));
    return r;
}
__device__ __forceinline__ unsigned long long fma2(unsigned long long a,
                                                   unsigned long long b,
                                                   unsigned long long c) {
    unsigned long long d;
    asm("fma.rn.f32x2 %0, %1, %2, %3;" : "=l"(d) : "l"(a), "l"(b), "l"(c));
    return d;
}
__device__ __forceinline__ void unpack2(unsigned long long u, float& lo, float& hi) {
    asm("mov.b64 {%0, %1}, %2;" : "=f"(lo), "=f"(hi) : "l"(u));
}

// ------------------------------- init ------------------------------------------
__global__ void init_kernel(int Nn) {
    int i = blockIdx.x * blockDim.x + threadIdx.x;
    if (i < Nn) d_deg[i] = 0;
}

// --------------------------- tiny precomputes ----------------------------------
__global__ void prep_kernel(const float* __restrict__ W_edge, const float* __restrict__ b_edge,
                            const float* __restrict__ W_pre,  const float* __restrict__ b_pre,
                            const float* __restrict__ b_post, const float* __restrict__ W_lin,
                            const float* __restrict__ b_lin) {
    int i = blockIdx.x * blockDim.x + threadIdx.x;
    if (i < 64 * 128) {
        int k = i >> 7, j = i & 127;
        d_Wds[i] = (j < 64) ? W_pre[k * 64 + j] : W_pre[(64 + k) * 64 + (j - 64)];
    } else if (i < 64 * 128 + 128) {
        int j = i - 64 * 128;
        float acc = b_lin[j];
        for (int k = 0; k < 128; k++) acc = fmaf(b_post[k], W_lin[k * 128 + j], acc);
        d_bc[j] = acc;
    } else if (i < 64 * 128 + 128 + 64) {
        int j = i - (64 * 128 + 128);
        float av = 0.f, ac = 0.f;
        for (int k = 0; k < 64; k++) {
            float w = W_pre[(128 + k) * 64 + j];
            av = fmaf(W_edge[k], w, av);
            ac = fmaf(b_edge[k], w, ac);
        }
        d_v[j]    = av;
        d_cvec[j] = ac + b_pre[j];
    }
}

// ------------- fast fp32x2 GEMM, BM=64, N fixed at 128, BK=16 ------------------
// C[M,128] = A_virt[M,K] @ B[K,128] (+bias). K % 16 == 0.
// MODE 0: A plain row-major with leading dim lda.
// MODE 1: virtual A row = [x(64) | agg(256) | agg*amp(256) | agg*iamp(256)], K=832.
// 256 threads, each computes 4 rows x 8 cols. Low-reg tiling for >=2 CTAs/SM.
template <int MODE>
__global__ __launch_bounds__(256) void sgemm_kernel(
    const float* __restrict__ A, const float* __restrict__ B,
    const float* __restrict__ bias, float* __restrict__ C,
    int M, int K, int lda) {
    __shared__ __align__(16) float As[2][16][68];    // transposed: As[k][m], pad 4
    __shared__ __align__(16) float Bs[2][16][128];

    const int tid  = threadIdx.x;
    const int row0 = blockIdx.x * 64;
    const int tr   = (tid >> 4) << 2;   // 0..60
    const int tc   = (tid & 15) << 3;   // 0..120

    unsigned long long acc2[4][4];
#pragma unroll
    for (int i = 0; i < 4; i++)
#pragma unroll
        for (int p = 0; p < 4; p++) acc2[i][p] = 0ull;

    // per-thread load coords: 1 A-float4, 2 B-float4 per k-tile
    const int am    = tid >> 2;                       // 0..63
    const int ak4   = (tid & 3) << 2;                 // 0,4,8,12
    const int bkr0  = tid >> 5;                       // 0..7
    const int bkr1  = bkr0 + 8;                       // 8..15
    const int bnq   = (tid & 31) << 2;

    float4 aS, bS0, bS1;

    auto loadT = [&](int k0) {
        int n = row0 + am;
        int c = k0 + ak4;
        float4 v = make_float4(0.f, 0.f, 0.f, 0.f);
        if (n < M) {
            if (MODE == 0) {
                v = *reinterpret_cast<const float4*>(A + (size_t)n * lda + c);
            } else {
                if (c < 64) {
                    v = *reinterpret_cast<const float4*>(A + (size_t)n * 64 + c);
                } else {
                    int cc = c - 64;
                    int g  = cc >> 8;
                    int o  = cc & 255;
                    v = *reinterpret_cast<const float4*>(d_agg + (size_t)n * 256 + o);
                    if (g != 0) {
                        float s = (g == 1) ? d_amp[n] : d_iamp[n];
                        v.x *= s; v.y *= s; v.z *= s; v.w *= s;
                    }
                }
            }
        }
        aS  = v;
        bS0 = *reinterpret_cast<const float4*>(B + (size_t)(k0 + bkr0) * 128 + bnq);
        bS1 = *reinterpret_cast<const float4*>(B + (size_t)(k0 + bkr1) * 128 + bnq);
    };
    auto storeT = [&](int buf) {
        As[buf][ak4 + 0][am] = aS.x;
        As[buf][ak4 + 1][am] = aS.y;
        As[buf][ak4 + 2][am] = aS.z;
        As[buf][ak4 + 3][am] = aS.w;
        *reinterpret_cast<float4*>(&Bs[buf][bkr0][bnq]) = bS0;
        *reinterpret_cast<float4*>(&Bs[buf][bkr1][bnq]) = bS1;
    };

    const int KT = K >> 4;
    loadT(0);
    storeT(0);
    __syncthreads();

    int buf = 0;
    for (int kt = 0; kt < KT; kt++) {
        if (kt + 1 < KT) loadT((kt + 1) << 4);
#pragma unroll
        for (int kk = 0; kk < 16; kk++) {
            float4 a0 = *reinterpret_cast<const float4*>(&As[buf][kk][tr]);
            ulonglong2 b0 = *reinterpret_cast<const ulonglong2*>(&Bs[buf][kk][tc]);
            ulonglong2 b1 = *reinterpret_cast<const ulonglong2*>(&Bs[buf][kk][tc + 4]);
            unsigned long long bv[4] = {b0.x, b0.y, b1.x, b1.y};
            float a[4] = {a0.x, a0.y, a0.z, a0.w};
#pragma unroll
            for (int i = 0; i < 4; i++) {
                unsigned long long aa = dup2(a[i]);
#pragma unroll
                for (int p = 0; p < 4; p++) acc2[i][p] = fma2(aa, bv[p], acc2[i][p]);
            }
        }
        if (kt + 1 < KT) {
            storeT(buf ^ 1);
            __syncthreads();
            buf ^= 1;
        }
    }

    // epilogue
#pragma unroll
    for (int i = 0; i < 4; i++) {
        int gr = row0 + tr + i;
        if (gr >= M) continue;
        float cv[8];
#pragma unroll
        for (int p = 0; p < 4; p++) unpack2(acc2[i][p], cv[2 * p], cv[2 * p + 1]);
        if (bias) {
#pragma unroll
            for (int q = 0; q < 8; q++) cv[q] += bias[tc + q];
        }
        *reinterpret_cast<float4*>(C + (size_t)gr * 128 + tc) =
            make_float4(cv[0], cv[1], cv[2], cv[3]);
        *reinterpret_cast<float4*>(C + (size_t)gr * 128 + tc + 4) =
            make_float4(cv[4], cv[5], cv[6], cv[7]);
    }
}

// ------------------------------- CSR build -------------------------------------
__global__ void count_kernel(const int* __restrict__ ei, int E) {
    int e = blockIdx.x * blockDim.x + threadIdx.x;
    if (e >= E) return;
    atomicAdd(&d_deg[ei[E + e]], 1);
}

__global__ void scan_kernel(int Nn) {
    __shared__ int sh[1024];
    int t = threadIdx.x;
    int C = (Nn + 1023) >> 10;
    int start = t * C;
    int end = start + C; if (end > Nn) end = Nn;
    int local = 0;
    for (int i = start; i < end; i++) local += d_deg[i];
    sh[t] = local;
    __syncthreads();
    for (int d = 1; d < 1024; d <<= 1) {
        int v = (t >= d) ? sh[t - d] : 0;
        __syncthreads();
        sh[t] += v;
        __syncthreads();
    }
    int run = (t == 0) ? 0 : sh[t - 1];
    for (int i = start; i < end; i++) {
        d_off[i] = run;
        d_fill[i] = run;
        run += d_deg[i];
    }
}

__global__ void scatter_kernel(const int* __restrict__ ei, const float* __restrict__ ea, int E) {
    int e = blockIdx.x * blockDim.x + threadIdx.x;
    if (e >= E) return;
    int d = ei[E + e];
    int pos = atomicAdd(&d_fill[d], 1);
    d_srcS[pos] = ei[e];
    d_eaS[pos]  = ea[e];
}

// -------- per-node aggregation (no atomics) -> compact agg + amp scalars -------
// 256 threads = 4 nodes x 64 feature-threads.
__global__ __launch_bounds__(256) void agg_kernel(int Nn) {
    int tid = threadIdx.x;
    int n = blockIdx.x * 4 + (tid >> 6);
    if (n >= Nn) return;
    int f = tid & 63;

    int off = d_off[n];
    int deg = d_deg[n];
    float pdf = d_pq[n * 128 + f];
    float vf  = d_v[f];
    float cf  = d_cvec[f];

    float sum = 0.f, sq = 0.f;
    float mn = INFINITY, mx = -INFINITY;
#pragma unroll 2
    for (int jj = 0; jj < deg; jj++) {
        int   s   = d_srcS[off + jj];
        float eav = d_eaS[off + jj];
        float m = pdf + d_pq[s * 128 + 64 + f] + eav * vf + cf;
        sum += m;
        sq = fmaf(m, m, sq);
        mn = fminf(mn, m);
        mx = fmaxf(mx, m);
    }

    float ct    = (float)deg;
    float cnt1  = fmaxf(ct, 1.f);
    float inv   = 1.f / cnt1;
    float mean  = sum * inv;
    float mean2 = sq * inv;
    float var   = mean2 - mean * mean;
    float sd    = sqrtf(fmaxf(var, 0.f) + 1e-5f);
    float vmn   = (deg > 0) ? mn : 0.f;
    float vmx   = (deg > 0) ? mx : 0.f;
    float amp   = logf(cnt1 + 1.f) * (1.0f / 2.19722457733621938f);  // / log(9)

    float* Ap = d_agg + (size_t)n * 256;
    Ap[f]       = mean;
    Ap[64 + f]  = vmn;
    Ap[128 + f] = vmx;
    Ap[192 + f] = sd;
    if (f == 0) {
        d_amp[n]  = amp;
        d_iamp[n] = 1.f / amp;
    }
}

// ------------------- pooling: one block per graph, no atomics ------------------
// batch is sorted; block g binary-searches its contiguous node range.
__global__ __launch_bounds__(256) void pool_kernel(const int* __restrict__ batch, int Nn) {
    int g = blockIdx.x;
    int tid = threadIdx.x;
    int j = tid & 127, half = tid >> 7;

    // lower_bound(batch, g) and lower_bound(batch, g+1)
    int lo = 0, hi = Nn;
    while (lo < hi) { int mid = (lo + hi) >> 1; if (batch[mid] < g) lo = mid + 1; else hi = mid; }
    int lo2 = lo, hi2 = Nn;
    while (lo2 < hi2) { int mid = (lo2 + hi2) >> 1; if (batch[mid] < g + 1) lo2 = mid + 1; else hi2 = mid; }

    float s = 0.f;
    for (int i = lo + half; i < lo2; i += 2) s += d_h[(size_t)i * 128 + j];

    __shared__ float red[256];
    red[tid] = s;
    __syncthreads();
    if (tid < 128) {
        d_zsum[g * 128 + j] = red[tid] + red[tid + 128];
        if (tid == 0) d_gcnt[g] = (float)(lo2 - lo);
    }
}

// ------------------------------- MLP head --------------------------------------
__device__ __forceinline__ void mlp_stats(float ps, float pq2, int rr, int j,
                                          float* redS, float* redQ,
                                          float* sgS, float* sbS,
                                          const float* __restrict__ g,
                                          const float* __restrict__ be) {
    redS[rr * 128 + j] = ps;
    redQ[rr * 128 + j] = pq2;
    __syncthreads();
    if (rr == 0) {
        float s = 0.f, q = 0.f;
#pragma unroll
        for (int r = 0; r < 8; r++) { s += redS[r * 128 + j]; q += redQ[r * 128 + j]; }
        float mu  = s * (1.f / 64.f);
        float var = q * (1.f / 64.f) - mu * mu;
        float is  = rsqrtf(fmaxf(var, 0.f) + 1e-5f);
        float sg  = g[j] * is;
        sgS[j] = sg;
        sbS[j] = be[j] - mu * sg;
    }
    __syncthreads();
}

__device__ __forceinline__ void mlp_layer(float* zS, float* redS, float* redQ,
                                          float* sgS, float* sbS,
                                          const float* __restrict__ W, const float* __restrict__ b,
                                          const float* __restrict__ g, const float* __restrict__ be,
                                          int rr, int j, float* rsave, const float* radd) {
    float acc[8];
#pragma unroll
    for (int u = 0; u < 8; u++) {
        int i = rr + u * 8;
        float a = b[j];
        for (int k = 0; k < 128; k++) a = fmaf(zS[i * 128 + k], W[k * 128 + j], a);
        acc[u] = a;
    }
    float ps = 0.f, pq2 = 0.f;
#pragma unroll
    for (int u = 0; u < 8; u++) { ps += acc[u]; pq2 = fmaf(acc[u], acc[u], pq2); }
    mlp_stats(ps, pq2, rr, j, redS, redQ, sgS, sbS, g, be);   // syncs cover zS reads
#pragma unroll
    for (int u = 0; u < 8; u++) {
        float val = acc[u] * sgS[j] + sbS[j];
        if (radd) val += radd[u];
        val = fmaxf(val, 0.f);
        zS[(rr + u * 8) * 128 + j] = val;
        if (rsave) rsave[u] = val;
    }
    __syncthreads();
}

__global__ __launch_bounds__(1024) void mlp_kernel(
        const float* __restrict__ g1,  const float* __restrict__ be1,
        const float* __restrict__ W2,  const float* __restrict__ b2,
        const float* __restrict__ g2,  const float* __restrict__ be2,
        const float* __restrict__ Wr1, const float* __restrict__ br1,
        const float* __restrict__ gr1, const float* __restrict__ ber1,
        const float* __restrict__ Wr2, const float* __restrict__ br2,
        const float* __restrict__ gr2, const float* __restrict__ ber2,
        const float* __restrict__ Wout, const float* __restrict__ bout,
        float* __restrict__ out) {
    __shared__ float zS[64 * 128];
    __shared__ float redS[8 * 128];
    __shared__ float redQ[8 * 128];
    __shared__ float sgS[128], sbS[128];
    int tid = threadIdx.x;
    int rr = tid >> 7, j = tid & 127;

    float v8[8];
#pragma unroll
    for (int u = 0; u < 8; u++) {
        int i = rr + u * 8;
        float gc = fmaxf(d_gcnt[i], 1.f);
        v8[u] = d_zsum[i * 128 + j] / gc;
    }
    {
        float ps = 0.f, pq2 = 0.f;
#pragma unroll
        for (int u = 0; u < 8; u++) { ps += v8[u]; pq2 = fmaf(v8[u], v8[u], pq2); }
        mlp_stats(ps, pq2, rr, j, redS, redQ, sgS, sbS, g1, be1);
#pragma unroll
        for (int u = 0; u < 8; u++)
            zS[(rr + u * 8) * 128 + j] = fmaxf(v8[u] * sgS[j] + sbS[j], 0.f);
        __syncthreads();
    }

    float res[8];
    mlp_layer(zS, redS, redQ, sgS, sbS, W2,  b2,  g2,  be2,  rr, j, res,    nullptr);
    mlp_layer(zS, redS, redQ, sgS, sbS, Wr1, br1, gr1, ber1, rr, j, nullptr, nullptr);
    mlp_layer(zS, redS, redQ, sgS, sbS, Wr2, br2, gr2, ber2, rr, j, nullptr, res);

    if (tid < 64) {
        float a = bout[0];
        for (int k = 0; k < 128; k++) a = fmaf(zS[tid * 128 + k], Wout[k], a);
        out[tid] = a;
    }
}

// --------------------------------- launch --------------------------------------
extern "C" void kernel_launch(void* const* d_in, const int* in_sizes, int n_in,
                              void* d_out, int out_size) {
    const float* x      = (const float*)d_in[0];
    const int*   ei     = (const int*)d_in[1];
    const float* ea     = (const float*)d_in[2];
    const int*   batch  = (const int*)d_in[3];
    const float* W_edge = (const float*)d_in[4];
    const float* b_edge = (const float*)d_in[5];
    const float* W_pre  = (const float*)d_in[6];
    const float* b_pre  = (const float*)d_in[7];
    const float* W_post = (const float*)d_in[8];
    const float* b_post = (const float*)d_in[9];
    const float* W_lin  = (const float*)d_in[10];
    const float* b_lin  = (const float*)d_in[11];
    const float* g1  = (const float*)d_in[12];
    const float* be1 = (const float*)d_in[13];
    const float* W2  = (const float*)d_in[14];
    const float* b2  = (const float*)d_in[15];
    const float* g2  = (const float*)d_in[16];
    const float* be2 = (const float*)d_in[17];
    const float* Wr1 = (const float*)d_in[18];
    const float* br1 = (const float*)d_in[19];
    const float* gr1 = (const float*)d_in[20];
    const float* ber1= (const float*)d_in[21];
    const float* Wr2 = (const float*)d_in[22];
    const float* br2 = (const float*)d_in[23];
    const float* gr2 = (const float*)d_in[24];
    const float* ber2= (const float*)d_in[25];
    const float* Wout= (const float*)d_in[26];
    const float* bout= (const float*)d_in[27];
    float* out = (float*)d_out;

    const int Nn = in_sizes[0] / 64;
    const int E  = in_sizes[2];

    void *p_pq, *p_Wds, *p_Wc, *p_bc, *p_h;
    cudaGetSymbolAddress(&p_pq,   d_pq);
    cudaGetSymbolAddress(&p_Wds,  d_Wds);
    cudaGetSymbolAddress(&p_Wc,   d_Wc);
    cudaGetSymbolAddress(&p_bc,   d_bc);
    cudaGetSymbolAddress(&p_h,    d_h);

    init_kernel<<<(Nn + 255) / 256, 256>>>(Nn);
    prep_kernel<<<(64 * 128 + 128 + 64 + 255) / 256, 256>>>(W_edge, b_edge, W_pre, b_pre,
                                                            b_post, W_lin, b_lin);
    // Wc = W_post @ W_lin   [832,128] @ [128,128]
    sgemm_kernel<0><<<(832 + 63) / 64, 256>>>(W_post, W_lin, nullptr, (float*)p_Wc,
                                              832, 128, 128);
    // pq = x @ [Wd|Ws]      [N,64] @ [64,128]
    sgemm_kernel<0><<<(Nn + 63) / 64, 256>>>(x, (const float*)p_Wds, nullptr,
                                             (float*)p_pq, Nn, 64, 64);
    count_kernel<<<(E + 255) / 256, 256>>>(ei, E);
    scan_kernel<<<1, 1024>>>(Nn);
    scatter_kernel<<<(E + 255) / 256, 256>>>(ei, ea, E);
    agg_kernel<<<(Nn + 3) / 4, 256>>>(Nn);
    // h = virt_feat @ Wc + bc   [N,832] @ [832,128], A built on the fly
    sgemm_kernel<1><<<(Nn + 63) / 64, 256>>>(x, (const float*)p_Wc,
                                             (const float*)p_bc, (float*)p_h,
                                             Nn, 832, 0);
    pool_kernel<<<GNUM, 256>>>(batch, Nn);
    mlp_kernel<<<1, 1024>>>(g1, be1, W2, b2, g2, be2, Wr1, br1, gr1, ber1,
                            Wr2, br2, gr2, ber2, Wout, bout, out);
}

// round 11
// speedup vs baseline: 1.2911x; 1.2911x over previous
#include <cuda_runtime.h>
#include <math.h>

// Problem constants (shapes fixed by dataset)
#define NMAX 50000
#define EMAX 800000
#define GNUM 64
// F=64, HG=HL=128; virtual feat width = 64 + 12*64 = 832

// ---------------- scratch (__device__ globals; no allocation allowed) ----------
__device__ float    d_pq[NMAX * 128];          // [p | q] per node
__device__ int      d_deg[NMAX];
__device__ int      d_off[NMAX];
__device__ int      d_fill[NMAX];
__device__ int      d_srcS[EMAX];              // src reordered by dst-CSR position
__device__ float    d_eaS[EMAX];               // edge_attr reordered likewise
__device__ float    d_agg[(size_t)NMAX * 256]; // [mean|mn|mx|sd] per node
__device__ float    d_amp[NMAX];
__device__ float    d_iamp[NMAX];
__device__ float    d_Y[(size_t)NMAX * 384];   // agg @ [Wc1|Wc2|Wc3]
__device__ float    d_h[NMAX * 128];
__device__ float    d_Wds[64 * 128];           // [Wd | Ws]
__device__ float    d_Wc[832 * 128];           // W_post @ W_lin
__device__ float    d_Wb[256 * 384];           // reorg: [Wc1|Wc2|Wc3] as [256,384]
__device__ float    d_bc[128];                 // b_post @ W_lin + b_lin
__device__ float    d_v[64];                   // W_edge @ W_pre_e
__device__ float    d_cvec[64];                // b_edge @ W_pre_e + b_pre
__device__ float    d_zsum[GNUM * 128];
__device__ float    d_gcnt[GNUM];

// ------------------------- f32x2 packed helpers --------------------------------
__device__ __forceinline__ unsigned long long dup2(float x) {
    unsigned long long r;
    asm("mov.b64 %0, {%1, %1};" : "=l"(r) : "f"(x));
    return r;
}
__device__ __forceinline__ unsigned long long fma2(unsigned long long a,
                                                   unsigned long long b,
                                                   unsigned long long c) {
    unsigned long long d;
    asm("fma.rn.f32x2 %0, %1, %2, %3;" : "=l"(d) : "l"(a), "l"(b), "l"(c));
    return d;
}
__device__ __forceinline__ void unpack2(unsigned long long u, float& lo, float& hi) {
    asm("mov.b64 {%0, %1}, %2;" : "=f"(lo), "=f"(hi) : "l"(u));
}
__device__ __forceinline__ void cpasync16(unsigned dst, const void* src) {
    asm volatile("cp.async.ca.shared.global [%0], [%1], 16;" :: "r"(dst), "l"(src));
}

// ------------------------------- init ------------------------------------------
__global__ void init_kernel(int Nn) {
    int i = blockIdx.x * blockDim.x + threadIdx.x;
    if (i < Nn) d_deg[i] = 0;
}

// --------------------------- tiny precomputes ----------------------------------
__global__ void prep_kernel(const float* __restrict__ W_edge, const float* __restrict__ b_edge,
                            const float* __restrict__ W_pre,  const float* __restrict__ b_pre,
                            const float* __restrict__ b_post, const float* __restrict__ W_lin,
                            const float* __restrict__ b_lin) {
    int i = blockIdx.x * blockDim.x + threadIdx.x;
    if (i < 64 * 128) {
        int k = i >> 7, j = i & 127;
        d_Wds[i] = (j < 64) ? W_pre[k * 64 + j] : W_pre[(64 + k) * 64 + (j - 64)];
    } else if (i < 64 * 128 + 128) {
        int j = i - 64 * 128;
        float acc = b_lin[j];
        for (int k = 0; k < 128; k++) acc = fmaf(b_post[k], W_lin[k * 128 + j], acc);
        d_bc[j] = acc;
    } else if (i < 64 * 128 + 128 + 64) {
        int j = i - (64 * 128 + 128);
        float av = 0.f, ac = 0.f;
        for (int k = 0; k < 64; k++) {
            float w = W_pre[(128 + k) * 64 + j];
            av = fmaf(W_edge[k], w, av);
            ac = fmaf(b_edge[k], w, ac);
        }
        d_v[j]    = av;
        d_cvec[j] = ac + b_pre[j];
    }
}

// Build d_Wb[256,384]: columns g*128+jj come from Wc rows (64 + g*256 + k).
__global__ void reorg_kernel() {
    int i = blockIdx.x * blockDim.x + threadIdx.x;
    if (i >= 256 * 384) return;
    int k = i / 384, j = i % 384;
    int g = j >> 7, jj = j & 127;
    d_Wb[i] = d_Wc[(64 + g * 256 + k) * 128 + jj];
}

// ------------- fp32x2 GEMM: BM=128, BN=128, BK=16, 256 thr, 8x8 ----------------
// C[M, ldc] tile = A[M, lda] @ B[K, ldb] (+bias).  cp.async double-buffered.
// EPI=1: fused PNA epilogue  C += bc + Y1 + amp*Y2 + iamp*Y3  (col0 must be 0).
template <int EPI>
__global__ __launch_bounds__(256, 2) void sgemm_kernel(
    const float* __restrict__ A, const float* __restrict__ B,
    const float* __restrict__ bias, float* __restrict__ C,
    int M, int K, int lda, int ldb, int ldc) {
    __shared__ __align__(16) float As[2][128][20];   // row-major tile, pad 4
    __shared__ __align__(16) float Bs[2][16][132];

    const int tid  = threadIdx.x;
    const int row0 = blockIdx.x * 128;
    const int col0 = blockIdx.y * 128;
    const int tr   = (tid >> 4) << 3;   // 0..120
    const int tc   = (tid & 15) << 3;   // 0..120

    const unsigned sA = (unsigned)__cvta_generic_to_shared(&As[0][0][0]);
    const unsigned sB = (unsigned)__cvta_generic_to_shared(&Bs[0][0][0]);

    unsigned long long acc2[8][4];
#pragma unroll
    for (int i = 0; i < 8; i++)
#pragma unroll
        for (int p = 0; p < 4; p++) acc2[i][p] = 0ull;

    auto issue = [&](int kt, int buf) {
        int k0 = kt << 4;
#pragma unroll
        for (int t = 0; t < 2; t++) {
            int c  = tid + t * 256;
            int m  = c >> 2, kq = (c & 3) << 2;
            if (row0 + m < M)
                cpasync16(sA + (unsigned)(buf * 2560 + m * 20 + kq) * 4,
                          A + (size_t)(row0 + m) * lda + k0 + kq);
            int kr = c >> 5, n4 = (c & 31) << 2;
            cpasync16(sB + (unsigned)(buf * 2112 + kr * 132 + n4) * 4,
                      B + (size_t)(k0 + kr) * ldb + col0 + n4);
        }
        asm volatile("cp.async.commit_group;");
    };

    const int KT = K >> 4;
    issue(0, 0);

    int buf = 0;
    for (int kt = 0; kt < KT; kt++) {
        if (kt + 1 < KT) {
            issue(kt + 1, buf ^ 1);
            asm volatile("cp.async.wait_group 1;");
        } else {
            asm volatile("cp.async.wait_group 0;");
        }
        __syncthreads();     // tile kt visible to all threads

#pragma unroll
        for (int kk4 = 0; kk4 < 4; kk4++) {
            float4 a4[8];
#pragma unroll
            for (int i = 0; i < 8; i++)
                a4[i] = *reinterpret_cast<const float4*>(&As[buf][tr + i][kk4 << 2]);
#pragma unroll
            for (int kkl = 0; kkl < 4; kkl++) {
                int kk = (kk4 << 2) + kkl;
                ulonglong2 b0 = *reinterpret_cast<const ulonglong2*>(&Bs[buf][kk][tc]);
                ulonglong2 b1 = *reinterpret_cast<const ulonglong2*>(&Bs[buf][kk][tc + 4]);
                unsigned long long bv[4] = {b0.x, b0.y, b1.x, b1.y};
#pragma unroll
                for (int i = 0; i < 8; i++) {
                    float av = reinterpret_cast<const float*>(&a4[i])[kkl];
                    unsigned long long aa = dup2(av);
#pragma unroll
                    for (int p = 0; p < 4; p++) acc2[i][p] = fma2(aa, bv[p], acc2[i][p]);
                }
            }
        }
        __syncthreads();     // everyone done reading buf before it is refilled
        buf ^= 1;
    }

    // epilogue
#pragma unroll
    for (int i = 0; i < 8; i++) {
        int gr = row0 + tr + i;
        if (gr >= M) continue;
        float cv[8];
#pragma unroll
        for (int p = 0; p < 4; p++) unpack2(acc2[i][p], cv[2 * p], cv[2 * p + 1]);
        if (EPI) {
            const float* Yp = d_Y + (size_t)gr * 384;
            float am = d_amp[gr], ia = d_iamp[gr];
#pragma unroll
            for (int q = 0; q < 8; q++) {
                int c = tc + q;
                cv[q] += bias[c] + Yp[c] + am * Yp[128 + c] + ia * Yp[256 + c];
            }
        } else if (bias) {
#pragma unroll
            for (int q = 0; q < 8; q++) cv[q] += bias[col0 + tc + q];
        }
        float* Cp = C + (size_t)gr * ldc + col0 + tc;
        *reinterpret_cast<float4*>(Cp)     = make_float4(cv[0], cv[1], cv[2], cv[3]);
        *reinterpret_cast<float4*>(Cp + 4) = make_float4(cv[4], cv[5], cv[6], cv[7]);
    }
}

// ------------------------------- CSR build -------------------------------------
__global__ void count_kernel(const int* __restrict__ ei, int E) {
    int e = blockIdx.x * blockDim.x + threadIdx.x;
    if (e >= E) return;
    atomicAdd(&d_deg[ei[E + e]], 1);
}

__global__ void scan_kernel(int Nn) {
    __shared__ int sh[1024];
    int t = threadIdx.x;
    int C = (Nn + 1023) >> 10;
    int start = t * C;
    int end = start + C; if (end > Nn) end = Nn;
    int local = 0;
    for (int i = start; i < end; i++) local += d_deg[i];
    sh[t] = local;
    __syncthreads();
    for (int d = 1; d < 1024; d <<= 1) {
        int v = (t >= d) ? sh[t - d] : 0;
        __syncthreads();
        sh[t] += v;
        __syncthreads();
    }
    int run = (t == 0) ? 0 : sh[t - 1];
    for (int i = start; i < end; i++) {
        d_off[i] = run;
        d_fill[i] = run;
        run += d_deg[i];
    }
}

__global__ void scatter_kernel(const int* __restrict__ ei, const float* __restrict__ ea, int E) {
    int e = blockIdx.x * blockDim.x + threadIdx.x;
    if (e >= E) return;
    int d = ei[E + e];
    int pos = atomicAdd(&d_fill[d], 1);
    d_srcS[pos] = ei[e];
    d_eaS[pos]  = ea[e];
}

// -------- per-node aggregation (no atomics) -> compact agg + amp scalars -------
// 256 threads = 4 nodes x 64 feature-threads.
__global__ __launch_bounds__(256) void agg_kernel(int Nn) {
    int tid = threadIdx.x;
    int n = blockIdx.x * 4 + (tid >> 6);
    if (n >= Nn) return;
    int f = tid & 63;

    int off = d_off[n];
    int deg = d_deg[n];
    float pdf = d_pq[n * 128 + f];
    float vf  = d_v[f];
    float cf  = d_cvec[f];

    float sum = 0.f, sq = 0.f;
    float mn = INFINITY, mx = -INFINITY;
#pragma unroll 2
    for (int jj = 0; jj < deg; jj++) {
        int   s   = d_srcS[off + jj];
        float eav = d_eaS[off + jj];
        float m = pdf + d_pq[s * 128 + 64 + f] + eav * vf + cf;
        sum += m;
        sq = fmaf(m, m, sq);
        mn = fminf(mn, m);
        mx = fmaxf(mx, m);
    }

    float ct    = (float)deg;
    float cnt1  = fmaxf(ct, 1.f);
    float inv   = 1.f / cnt1;
    float mean  = sum * inv;
    float mean2 = sq * inv;
    float var   = mean2 - mean * mean;
    float sd    = sqrtf(fmaxf(var, 0.f) + 1e-5f);
    float vmn   = (deg > 0) ? mn : 0.f;
    float vmx   = (deg > 0) ? mx : 0.f;
    float amp   = logf(cnt1 + 1.f) * (1.0f / 2.19722457733621938f);  // / log(9)

    float* Ap = d_agg + (size_t)n * 256;
    Ap[f]       = mean;
    Ap[64 + f]  = vmn;
    Ap[128 + f] = vmx;
    Ap[192 + f] = sd;
    if (f == 0) {
        d_amp[n]  = amp;
        d_iamp[n] = 1.f / amp;
    }
}

// ------------------- pooling: one block per graph, no atomics ------------------
__global__ __launch_bounds__(256) void pool_kernel(const int* __restrict__ batch, int Nn) {
    int g = blockIdx.x;
    int tid = threadIdx.x;
    int j = tid & 127, half = tid >> 7;

    int lo = 0, hi = Nn;
    while (lo < hi) { int mid = (lo + hi) >> 1; if (batch[mid] < g) lo = mid + 1; else hi = mid; }
    int lo2 = lo, hi2 = Nn;
    while (lo2 < hi2) { int mid = (lo2 + hi2) >> 1; if (batch[mid] < g + 1) lo2 = mid + 1; else hi2 = mid; }

    float s = 0.f;
    for (int i = lo + half; i < lo2; i += 2) s += d_h[(size_t)i * 128 + j];

    __shared__ float red[256];
    red[tid] = s;
    __syncthreads();
    if (tid < 128) {
        d_zsum[g * 128 + j] = red[tid] + red[tid + 128];
        if (tid == 0) d_gcnt[g] = (float)(lo2 - lo);
    }
}

// ------------------------------- MLP head --------------------------------------
__device__ __forceinline__ void mlp_stats(float ps, float pq2, int rr, int j,
                                          float* redS, float* redQ,
                                          float* sgS, float* sbS,
                                          const float* __restrict__ g,
                                          const float* __restrict__ be) {
    redS[rr * 128 + j] = ps;
    redQ[rr * 128 + j] = pq2;
    __syncthreads();
    if (rr == 0) {
        float s = 0.f, q = 0.f;
#pragma unroll
        for (int r = 0; r < 8; r++) { s += redS[r * 128 + j]; q += redQ[r * 128 + j]; }
        float mu  = s * (1.f / 64.f);
        float var = q * (1.f / 64.f) - mu * mu;
        float is  = rsqrtf(fmaxf(var, 0.f) + 1e-5f);
        float sg  = g[j] * is;
        sgS[j] = sg;
        sbS[j] = be[j] - mu * sg;
    }
    __syncthreads();
}

__device__ __forceinline__ void mlp_layer(float* zS, float* redS, float* redQ,
                                          float* sgS, float* sbS,
                                          const float* __restrict__ W, const float* __restrict__ b,
                                          const float* __restrict__ g, const float* __restrict__ be,
                                          int rr, int j, float* rsave, const float* radd) {
    float acc[8];
#pragma unroll
    for (int u = 0; u < 8; u++) {
        int i = rr + u * 8;
        float a = b[j];
        for (int k = 0; k < 128; k++) a = fmaf(zS[i * 128 + k], W[k * 128 + j], a);
        acc[u] = a;
    }
    float ps = 0.f, pq2 = 0.f;
#pragma unroll
    for (int u = 0; u < 8; u++) { ps += acc[u]; pq2 = fmaf(acc[u], acc[u], pq2); }
    mlp_stats(ps, pq2, rr, j, redS, redQ, sgS, sbS, g, be);   // syncs cover zS reads
#pragma unroll
    for (int u = 0; u < 8; u++) {
        float val = acc[u] * sgS[j] + sbS[j];
        if (radd) val += radd[u];
        val = fmaxf(val, 0.f);
        zS[(rr + u * 8) * 128 + j] = val;
        if (rsave) rsave[u] = val;
    }
    __syncthreads();
}

__global__ __launch_bounds__(1024) void mlp_kernel(
        const float* __restrict__ g1,  const float* __restrict__ be1,
        const float* __restrict__ W2,  const float* __restrict__ b2,
        const float* __restrict__ g2,  const float* __restrict__ be2,
        const float* __restrict__ Wr1, const float* __restrict__ br1,
        const float* __restrict__ gr1, const float* __restrict__ ber1,
        const float* __restrict__ Wr2, const float* __restrict__ br2,
        const float* __restrict__ gr2, const float* __restrict__ ber2,
        const float* __restrict__ Wout, const float* __restrict__ bout,
        float* __restrict__ out) {
    __shared__ float zS[64 * 128];
    __shared__ float redS[8 * 128];
    __shared__ float redQ[8 * 128];
    __shared__ float sgS[128], sbS[128];
    int tid = threadIdx.x;
    int rr = tid >> 7, j = tid & 127;

    float v8[8];
#pragma unroll
    for (int u = 0; u < 8; u++) {
        int i = rr + u * 8;
        float gc = fmaxf(d_gcnt[i], 1.f);
        v8[u] = d_zsum[i * 128 + j] / gc;
    }
    {
        float ps = 0.f, pq2 = 0.f;
#pragma unroll
        for (int u = 0; u < 8; u++) { ps += v8[u]; pq2 = fmaf(v8[u], v8[u], pq2); }
        mlp_stats(ps, pq2, rr, j, redS, redQ, sgS, sbS, g1, be1);
#pragma unroll
        for (int u = 0; u < 8; u++)
            zS[(rr + u * 8) * 128 + j] = fmaxf(v8[u] * sgS[j] + sbS[j], 0.f);
        __syncthreads();
    }

    float res[8];
    mlp_layer(zS, redS, redQ, sgS, sbS, W2,  b2,  g2,  be2,  rr, j, res,    nullptr);
    mlp_layer(zS, redS, redQ, sgS, sbS, Wr1, br1, gr1, ber1, rr, j, nullptr, nullptr);
    mlp_layer(zS, redS, redQ, sgS, sbS, Wr2, br2, gr2, ber2, rr, j, nullptr, res);

    if (tid < 64) {
        float a = bout[0];
        for (int k = 0; k < 128; k++) a = fmaf(zS[tid * 128 + k], Wout[k], a);
        out[tid] = a;
    }
}

// --------------------------------- launch --------------------------------------
extern "C" void kernel_launch(void* const* d_in, const int* in_sizes, int n_in,
                              void* d_out, int out_size) {
    const float* x      = (const float*)d_in[0];
    const int*   ei     = (const int*)d_in[1];
    const float* ea     = (const float*)d_in[2];
    const int*   batch  = (const int*)d_in[3];
    const float* W_edge = (const float*)d_in[4];
    const float* b_edge = (const float*)d_in[5];
    const float* W_pre  = (const float*)d_in[6];
    const float* b_pre  = (const float*)d_in[7];
    const float* W_post = (const float*)d_in[8];
    const float* b_post = (const float*)d_in[9];
    const float* W_lin  = (const float*)d_in[10];
    const float* b_lin  = (const float*)d_in[11];
    const float* g1  = (const float*)d_in[12];
    const float* be1 = (const float*)d_in[13];
    const float* W2  = (const float*)d_in[14];
    const float* b2  = (const float*)d_in[15];
    const float* g2  = (const float*)d_in[16];
    const float* be2 = (const float*)d_in[17];
    const float* Wr1 = (const float*)d_in[18];
    const float* br1 = (const float*)d_in[19];
    const float* gr1 = (const float*)d_in[20];
    const float* ber1= (const float*)d_in[21];
    const float* Wr2 = (const float*)d_in[22];
    const float* br2 = (const float*)d_in[23];
    const float* gr2 = (const float*)d_in[24];
    const float* ber2= (const float*)d_in[25];
    const float* Wout= (const float*)d_in[26];
    const float* bout= (const float*)d_in[27];
    float* out = (float*)d_out;

    const int Nn = in_sizes[0] / 64;
    const int E  = in_sizes[2];

    void *p_pq, *p_Wds, *p_Wc, *p_Wb, *p_bc, *p_agg, *p_Y, *p_h;
    cudaGetSymbolAddress(&p_pq,  d_pq);
    cudaGetSymbolAddress(&p_Wds, d_Wds);
    cudaGetSymbolAddress(&p_Wc,  d_Wc);
    cudaGetSymbolAddress(&p_Wb,  d_Wb);
    cudaGetSymbolAddress(&p_bc,  d_bc);
    cudaGetSymbolAddress(&p_agg, d_agg);
    cudaGetSymbolAddress(&p_Y,   d_Y);
    cudaGetSymbolAddress(&p_h,   d_h);

    init_kernel<<<(Nn + 255) / 256, 256>>>(Nn);
    prep_kernel<<<(64 * 128 + 128 + 64 + 255) / 256, 256>>>(W_edge, b_edge, W_pre, b_pre,
                                                            b_post, W_lin, b_lin);
    // Wc = W_post @ W_lin   [832,128] @ [128,128]
    {
        dim3 g((832 + 127) / 128, 1);
        sgemm_kernel<0><<<g, 256>>>(W_post, W_lin, nullptr, (float*)p_Wc,
                                    832, 128, 128, 128, 128);
    }
    reorg_kernel<<<(256 * 384 + 255) / 256, 256>>>();
    // pq = x @ [Wd|Ws]      [N,64] @ [64,128]
    {
        dim3 g((Nn + 127) / 128, 1);
        sgemm_kernel<0><<<g, 256>>>(x, (const float*)p_Wds, nullptr, (float*)p_pq,
                                    Nn, 64, 64, 128, 128);
    }
    count_kernel<<<(E + 255) / 256, 256>>>(ei, E);
    scan_kernel<<<1, 1024>>>(Nn);
    scatter_kernel<<<(E + 255) / 256, 256>>>(ei, ea, E);
    agg_kernel<<<(Nn + 3) / 4, 256>>>(Nn);
    // Y = agg @ [Wc1|Wc2|Wc3]   [N,256] @ [256,384]
    {
        dim3 g((Nn + 127) / 128, 3);
        sgemm_kernel<0><<<g, 256>>>((const float*)p_agg, (const float*)p_Wb, nullptr,
                                    (float*)p_Y, Nn, 256, 256, 384, 384);
    }
    // h = x @ Wc0 + bc + Y1 + amp*Y2 + iamp*Y3   (fused epilogue)
    {
        dim3 g((Nn + 127) / 128, 1);
        sgemm_kernel<1><<<g, 256>>>(x, (const float*)p_Wc, (const float*)p_bc,
                                    (float*)p_h, Nn, 64, 64, 128, 128);
    }
    pool_kernel<<<GNUM, 256>>>(batch, Nn);
    mlp_kernel<<<1, 1024>>>(g1, be1, W2, b2, g2, be2, Wr1, br1, gr1, ber1,
                            Wr2, br2, gr2, ber2, Wout, bout, out);
}

// round 12
// speedup vs baseline: 1.8471x; 1.4306x over previous
#include <cuda_runtime.h>
#include <math.h>

// Problem constants (shapes fixed by dataset)
#define NMAX 50000
#define EMAX 800000
#define GNUM 64
// F=64, HG=HL=128; virtual feat width = 64 + 12*64 = 832

// ---------------- scratch (__device__ globals; no allocation allowed) ----------
__device__ float    d_pq[NMAX * 128];          // [p | q] per node
__device__ int      d_deg[NMAX];
__device__ int      d_off[NMAX];
__device__ int      d_fill[NMAX];
__device__ int      d_srcS[EMAX];              // src reordered by dst-CSR position
__device__ float    d_eaS[EMAX];               // edge_attr reordered likewise
__device__ float    d_agg[(size_t)NMAX * 256]; // [mean|mn|mx|sd] per node
__device__ float    d_amp[NMAX];
__device__ float    d_iamp[NMAX];
__device__ float    d_fsum[GNUM * 832];        // per-graph summed virtual feat
__device__ float    d_z[GNUM * 128];           // z = featbar @ Wc + bc (pre-BN)
__device__ float    d_Wds[64 * 128];           // [Wd | Ws]
__device__ float    d_Wc[832 * 128];           // W_post @ W_lin
__device__ float    d_bc[128];                 // b_post @ W_lin + b_lin
__device__ float    d_v[64];                   // W_edge @ W_pre_e
__device__ float    d_cvec[64];                // b_edge @ W_pre_e + b_pre
__device__ float    d_gcnt[GNUM];

// ------------------------- f32x2 packed helpers --------------------------------
__device__ __forceinline__ unsigned long long dup2(float x) {
    unsigned long long r;
    asm("mov.b64 %0, {%1, %1};" : "=l"(r) : "f"(x));
    return r;
}
__device__ __forceinline__ unsigned long long fma2(unsigned long long a,
                                                   unsigned long long b,
                                                   unsigned long long c) {
    unsigned long long d;
    asm("fma.rn.f32x2 %0, %1, %2, %3;" : "=l"(d) : "l"(a), "l"(b), "l"(c));
    return d;
}
__device__ __forceinline__ void unpack2(unsigned long long u, float& lo, float& hi) {
    asm("mov.b64 {%0, %1}, %2;" : "=f"(lo), "=f"(hi) : "l"(u));
}
__device__ __forceinline__ void cpasync16(unsigned dst, const void* src) {
    asm volatile("cp.async.ca.shared.global [%0], [%1], 16;" :: "r"(dst), "l"(src));
}

// ------------------------------- init ------------------------------------------
__global__ void init_kernel(int Nn) {
    int i = blockIdx.x * blockDim.x + threadIdx.x;
    if (i < Nn) d_deg[i] = 0;
    if (i < GNUM * 832) d_fsum[i] = 0.f;
}

// --------------------------- tiny precomputes ----------------------------------
__global__ void prep_kernel(const float* __restrict__ W_edge, const float* __restrict__ b_edge,
                            const float* __restrict__ W_pre,  const float* __restrict__ b_pre,
                            const float* __restrict__ b_post, const float* __restrict__ W_lin,
                            const float* __restrict__ b_lin) {
    int i = blockIdx.x * blockDim.x + threadIdx.x;
    if (i < 64 * 128) {
        int k = i >> 7, j = i & 127;
        d_Wds[i] = (j < 64) ? W_pre[k * 64 + j] : W_pre[(64 + k) * 64 + (j - 64)];
    } else if (i < 64 * 128 + 128) {
        int j = i - 64 * 128;
        float acc = b_lin[j];
        for (int k = 0; k < 128; k++) acc = fmaf(b_post[k], W_lin[k * 128 + j], acc);
        d_bc[j] = acc;
    } else if (i < 64 * 128 + 128 + 64) {
        int j = i - (64 * 128 + 128);
        float av = 0.f, ac = 0.f;
        for (int k = 0; k < 64; k++) {
            float w = W_pre[(128 + k) * 64 + j];
            av = fmaf(W_edge[k], w, av);
            ac = fmaf(b_edge[k], w, ac);
        }
        d_v[j]    = av;
        d_cvec[j] = ac + b_pre[j];
    }
}

// ------------- fp32x2 GEMM: BM=128, BN=128, BK=16, 256 thr, 8x8 ----------------
// C[M, ldc] tile = A[M, lda] @ B[K, ldb] (+bias).  cp.async double-buffered.
__global__ __launch_bounds__(256, 2) void sgemm_kernel(
    const float* __restrict__ A, const float* __restrict__ B,
    const float* __restrict__ bias, float* __restrict__ C,
    int M, int K, int lda, int ldb, int ldc) {
    __shared__ __align__(16) float As[2][128][20];   // row-major tile, pad 4
    __shared__ __align__(16) float Bs[2][16][132];

    const int tid  = threadIdx.x;
    const int row0 = blockIdx.x * 128;
    const int col0 = blockIdx.y * 128;
    const int tr   = (tid >> 4) << 3;   // 0..120
    const int tc   = (tid & 15) << 3;   // 0..120

    const unsigned sA = (unsigned)__cvta_generic_to_shared(&As[0][0][0]);
    const unsigned sB = (unsigned)__cvta_generic_to_shared(&Bs[0][0][0]);

    unsigned long long acc2[8][4];
#pragma unroll
    for (int i = 0; i < 8; i++)
#pragma unroll
        for (int p = 0; p < 4; p++) acc2[i][p] = 0ull;

    auto issue = [&](int kt, int buf) {
        int k0 = kt << 4;
#pragma unroll
        for (int t = 0; t < 2; t++) {
            int c  = tid + t * 256;
            int m  = c >> 2, kq = (c & 3) << 2;
            if (row0 + m < M)
                cpasync16(sA + (unsigned)(buf * 2560 + m * 20 + kq) * 4,
                          A + (size_t)(row0 + m) * lda + k0 + kq);
            int kr = c >> 5, n4 = (c & 31) << 2;
            cpasync16(sB + (unsigned)(buf * 2112 + kr * 132 + n4) * 4,
                      B + (size_t)(k0 + kr) * ldb + col0 + n4);
        }
        asm volatile("cp.async.commit_group;");
    };

    const int KT = K >> 4;
    issue(0, 0);

    int buf = 0;
    for (int kt = 0; kt < KT; kt++) {
        if (kt + 1 < KT) {
            issue(kt + 1, buf ^ 1);
            asm volatile("cp.async.wait_group 1;");
        } else {
            asm volatile("cp.async.wait_group 0;");
        }
        __syncthreads();     // tile kt visible to all threads

#pragma unroll
        for (int kk4 = 0; kk4 < 4; kk4++) {
            float4 a4[8];
#pragma unroll
            for (int i = 0; i < 8; i++)
                a4[i] = *reinterpret_cast<const float4*>(&As[buf][tr + i][kk4 << 2]);
#pragma unroll
            for (int kkl = 0; kkl < 4; kkl++) {
                int kk = (kk4 << 2) + kkl;
                ulonglong2 b0 = *reinterpret_cast<const ulonglong2*>(&Bs[buf][kk][tc]);
                ulonglong2 b1 = *reinterpret_cast<const ulonglong2*>(&Bs[buf][kk][tc + 4]);
                unsigned long long bv[4] = {b0.x, b0.y, b1.x, b1.y};
#pragma unroll
                for (int i = 0; i < 8; i++) {
                    float av = reinterpret_cast<const float*>(&a4[i])[kkl];
                    unsigned long long aa = dup2(av);
#pragma unroll
                    for (int p = 0; p < 4; p++) acc2[i][p] = fma2(aa, bv[p], acc2[i][p]);
                }
            }
        }
        __syncthreads();
        buf ^= 1;
    }

    // epilogue
#pragma unroll
    for (int i = 0; i < 8; i++) {
        int gr = row0 + tr + i;
        if (gr >= M) continue;
        float cv[8];
#pragma unroll
        for (int p = 0; p < 4; p++) unpack2(acc2[i][p], cv[2 * p], cv[2 * p + 1]);
        if (bias) {
#pragma unroll
            for (int q = 0; q < 8; q++) cv[q] += bias[col0 + tc + q];
        }
        float* Cp = C + (size_t)gr * ldc + col0 + tc;
        *reinterpret_cast<float4*>(Cp)     = make_float4(cv[0], cv[1], cv[2], cv[3]);
        *reinterpret_cast<float4*>(Cp + 4) = make_float4(cv[4], cv[5], cv[6], cv[7]);
    }
}

// ------------------------------- CSR build -------------------------------------
__global__ void count_kernel(const int* __restrict__ ei, int E) {
    int e = blockIdx.x * blockDim.x + threadIdx.x;
    if (e >= E) return;
    atomicAdd(&d_deg[ei[E + e]], 1);
}

__global__ void scan_kernel(int Nn) {
    __shared__ int sh[1024];
    int t = threadIdx.x;
    int C = (Nn + 1023) >> 10;
    int start = t * C;
    int end = start + C; if (end > Nn) end = Nn;
    int local = 0;
    for (int i = start; i < end; i++) local += d_deg[i];
    sh[t] = local;
    __syncthreads();
    for (int d = 1; d < 1024; d <<= 1) {
        int v = (t >= d) ? sh[t - d] : 0;
        __syncthreads();
        sh[t] += v;
        __syncthreads();
    }
    int run = (t == 0) ? 0 : sh[t - 1];
    for (int i = start; i < end; i++) {
        d_off[i] = run;
        d_fill[i] = run;
        run += d_deg[i];
    }
}

__global__ void scatter_kernel(const int* __restrict__ ei, const float* __restrict__ ea, int E) {
    int e = blockIdx.x * blockDim.x + threadIdx.x;
    if (e >= E) return;
    int d = ei[E + e];
    int pos = atomicAdd(&d_fill[d], 1);
    d_srcS[pos] = ei[e];
    d_eaS[pos]  = ea[e];
}

// -------- per-node aggregation (no atomics) -> compact agg + amp scalars -------
// 256 threads = 4 nodes x 64 feature-threads.
__global__ __launch_bounds__(256) void agg_kernel(int Nn) {
    int tid = threadIdx.x;
    int n = blockIdx.x * 4 + (tid >> 6);
    if (n >= Nn) return;
    int f = tid & 63;

    int off = d_off[n];
    int deg = d_deg[n];
    float pdf = d_pq[n * 128 + f];
    float vf  = d_v[f];
    float cf  = d_cvec[f];

    float sum = 0.f, sq = 0.f;
    float mn = INFINITY, mx = -INFINITY;
#pragma unroll 2
    for (int jj = 0; jj < deg; jj++) {
        int   s   = d_srcS[off + jj];
        float eav = d_eaS[off + jj];
        float m = pdf + d_pq[s * 128 + 64 + f] + eav * vf + cf;
        sum += m;
        sq = fmaf(m, m, sq);
        mn = fminf(mn, m);
        mx = fmaxf(mx, m);
    }

    float ct    = (float)deg;
    float cnt1  = fmaxf(ct, 1.f);
    float inv   = 1.f / cnt1;
    float mean  = sum * inv;
    float mean2 = sq * inv;
    float var   = mean2 - mean * mean;
    float sd    = sqrtf(fmaxf(var, 0.f) + 1e-5f);
    float vmn   = (deg > 0) ? mn : 0.f;
    float vmx   = (deg > 0) ? mx : 0.f;
    float amp   = logf(cnt1 + 1.f) * (1.0f / 2.19722457733621938f);  // / log(9)

    float* Ap = d_agg + (size_t)n * 256;
    Ap[f]       = mean;
    Ap[64 + f]  = vmn;
    Ap[128 + f] = vmx;
    Ap[192 + f] = sd;
    if (f == 0) {
        d_amp[n]  = amp;
        d_iamp[n] = 1.f / amp;
    }
}

// ---------- pooled virtual features: sum over nodes of each graph --------------
// 4 blocks per graph; thread t owns agg column t (and x column t if t<64).
// fsum layout matches Wc row order: [x(64) | agg(256) | agg*amp(256) | agg*iamp(256)].
__global__ __launch_bounds__(256) void pool_feat_kernel(const int* __restrict__ batch,
                                                        const float* __restrict__ x, int Nn) {
    int g    = blockIdx.x >> 2;
    int part = blockIdx.x & 3;
    int tid  = threadIdx.x;

    int lo = 0, hi = Nn;
    while (lo < hi) { int mid = (lo + hi) >> 1; if (batch[mid] < g) lo = mid + 1; else hi = mid; }
    int lo2 = lo, hi2 = Nn;
    while (lo2 < hi2) { int mid = (lo2 + hi2) >> 1; if (batch[mid] < g + 1) lo2 = mid + 1; else hi2 = mid; }

    int cnt = lo2 - lo;
    int s = lo + (cnt * part) / 4;
    int e = lo + (cnt * (part + 1)) / 4;

    float a1 = 0.f, a2 = 0.f, a3 = 0.f, sx = 0.f;
    for (int n = s; n < e; n++) {
        float amp = d_amp[n];
        float ia  = d_iamp[n];
        float av  = d_agg[(size_t)n * 256 + tid];
        a1 += av;
        a2 = fmaf(av, amp, a2);
        a3 = fmaf(av, ia,  a3);
        if (tid < 64) sx += x[n * 64 + tid];
    }
    float* F = d_fsum + g * 832;
    atomicAdd(&F[64 + tid],  a1);
    atomicAdd(&F[320 + tid], a2);
    atomicAdd(&F[576 + tid], a3);
    if (tid < 64) atomicAdd(&F[tid], sx);
    if (part == 0 && tid == 0) d_gcnt[g] = (float)cnt;
}

// ------------- z = (fsum/cnt) @ Wc + bc   [64,832]@[832,128] -------------------
__global__ __launch_bounds__(128) void zsmall_kernel() {
    int g = blockIdx.x;
    int j = threadIdx.x;
    float inv = 1.f / fmaxf(d_gcnt[g], 1.f);
    const float* F = d_fsum + g * 832;
    float acc = d_bc[j];
    for (int k = 0; k < 832; k++)
        acc = fmaf(F[k] * inv, d_Wc[k * 128 + j], acc);
    d_z[g * 128 + j] = acc;
}

// ------------------------------- MLP head --------------------------------------
__device__ __forceinline__ void mlp_stats(float ps, float pq2, int rr, int j,
                                          float* redS, float* redQ,
                                          float* sgS, float* sbS,
                                          const float* __restrict__ g,
                                          const float* __restrict__ be) {
    redS[rr * 128 + j] = ps;
    redQ[rr * 128 + j] = pq2;
    __syncthreads();
    if (rr == 0) {
        float s = 0.f, q = 0.f;
#pragma unroll
        for (int r = 0; r < 8; r++) { s += redS[r * 128 + j]; q += redQ[r * 128 + j]; }
        float mu  = s * (1.f / 64.f);
        float var = q * (1.f / 64.f) - mu * mu;
        float is  = rsqrtf(fmaxf(var, 0.f) + 1e-5f);
        float sg  = g[j] * is;
        sgS[j] = sg;
        sbS[j] = be[j] - mu * sg;
    }
    __syncthreads();
}

__device__ __forceinline__ void mlp_layer(float* zS, float* redS, float* redQ,
                                          float* sgS, float* sbS,
                                          const float* __restrict__ W, const float* __restrict__ b,
                                          const float* __restrict__ g, const float* __restrict__ be,
                                          int rr, int j, float* rsave, const float* radd) {
    float acc[8];
#pragma unroll
    for (int u = 0; u < 8; u++) {
        int i = rr + u * 8;
        float a = b[j];
        for (int k = 0; k < 128; k++) a = fmaf(zS[i * 128 + k], W[k * 128 + j], a);
        acc[u] = a;
    }
    float ps = 0.f, pq2 = 0.f;
#pragma unroll
    for (int u = 0; u < 8; u++) { ps += acc[u]; pq2 = fmaf(acc[u], acc[u], pq2); }
    mlp_stats(ps, pq2, rr, j, redS, redQ, sgS, sbS, g, be);   // syncs cover zS reads
#pragma unroll
    for (int u = 0; u < 8; u++) {
        float val = acc[u] * sgS[j] + sbS[j];
        if (radd) val += radd[u];
        val = fmaxf(val, 0.f);
        zS[(rr + u * 8) * 128 + j] = val;
        if (rsave) rsave[u] = val;
    }
    __syncthreads();
}

__global__ __launch_bounds__(1024) void mlp_kernel(
        const float* __restrict__ g1,  const float* __restrict__ be1,
        const float* __restrict__ W2,  const float* __restrict__ b2,
        const float* __restrict__ g2,  const float* __restrict__ be2,
        const float* __restrict__ Wr1, const float* __restrict__ br1,
        const float* __restrict__ gr1, const float* __restrict__ ber1,
        const float* __restrict__ Wr2, const float* __restrict__ br2,
        const float* __restrict__ gr2, const float* __restrict__ ber2,
        const float* __restrict__ Wout, const float* __restrict__ bout,
        float* __restrict__ out) {
    __shared__ float zS[64 * 128];
    __shared__ float redS[8 * 128];
    __shared__ float redQ[8 * 128];
    __shared__ float sgS[128], sbS[128];
    int tid = threadIdx.x;
    int rr = tid >> 7, j = tid & 127;

    float v8[8];
#pragma unroll
    for (int u = 0; u < 8; u++) {
        int i = rr + u * 8;
        v8[u] = d_z[i * 128 + j];
    }
    {
        float ps = 0.f, pq2 = 0.f;
#pragma unroll
        for (int u = 0; u < 8; u++) { ps += v8[u]; pq2 = fmaf(v8[u], v8[u], pq2); }
        mlp_stats(ps, pq2, rr, j, redS, redQ, sgS, sbS, g1, be1);
#pragma unroll
        for (int u = 0; u < 8; u++)
            zS[(rr + u * 8) * 128 + j] = fmaxf(v8[u] * sgS[j] + sbS[j], 0.f);
        __syncthreads();
    }

    float res[8];
    mlp_layer(zS, redS, redQ, sgS, sbS, W2,  b2,  g2,  be2,  rr, j, res,    nullptr);
    mlp_layer(zS, redS, redQ, sgS, sbS, Wr1, br1, gr1, ber1, rr, j, nullptr, nullptr);
    mlp_layer(zS, redS, redQ, sgS, sbS, Wr2, br2, gr2, ber2, rr, j, nullptr, res);

    if (tid < 64) {
        float a = bout[0];
        for (int k = 0; k < 128; k++) a = fmaf(zS[tid * 128 + k], Wout[k], a);
        out[tid] = a;
    }
}

// --------------------------------- launch --------------------------------------
extern "C" void kernel_launch(void* const* d_in, const int* in_sizes, int n_in,
                              void* d_out, int out_size) {
    const float* x      = (const float*)d_in[0];
    const int*   ei     = (const int*)d_in[1];
    const float* ea     = (const float*)d_in[2];
    const int*   batch  = (const int*)d_in[3];
    const float* W_edge = (const float*)d_in[4];
    const float* b_edge = (const float*)d_in[5];
    const float* W_pre  = (const float*)d_in[6];
    const float* b_pre  = (const float*)d_in[7];
    const float* W_post = (const float*)d_in[8];
    const float* b_post = (const float*)d_in[9];
    const float* W_lin  = (const float*)d_in[10];
    const float* b_lin  = (const float*)d_in[11];
    const float* g1  = (const float*)d_in[12];
    const float* be1 = (const float*)d_in[13];
    const float* W2  = (const float*)d_in[14];
    const float* b2  = (const float*)d_in[15];
    const float* g2  = (const float*)d_in[16];
    const float* be2 = (const float*)d_in[17];
    const float* Wr1 = (const float*)d_in[18];
    const float* br1 = (const float*)d_in[19];
    const float* gr1 = (const float*)d_in[20];
    const float* ber1= (const float*)d_in[21];
    const float* Wr2 = (const float*)d_in[22];
    const float* br2 = (const float*)d_in[23];
    const float* gr2 = (const float*)d_in[24];
    const float* ber2= (const float*)d_in[25];
    const float* Wout= (const float*)d_in[26];
    const float* bout= (const float*)d_in[27];
    float* out = (float*)d_out;

    const int Nn = in_sizes[0] / 64;
    const int E  = in_sizes[2];

    void *p_pq, *p_Wds, *p_Wc;
    cudaGetSymbolAddress(&p_pq,  d_pq);
    cudaGetSymbolAddress(&p_Wds, d_Wds);
    cudaGetSymbolAddress(&p_Wc,  d_Wc);

    init_kernel<<<(GNUM * 832 + 255) / 256, 256>>>(Nn);
    prep_kernel<<<(64 * 128 + 128 + 64 + 255) / 256, 256>>>(W_edge, b_edge, W_pre, b_pre,
                                                            b_post, W_lin, b_lin);
    // Wc = W_post @ W_lin   [832,128] @ [128,128]
    {
        dim3 g((832 + 127) / 128, 1);
        sgemm_kernel<<<g, 256>>>(W_post, W_lin, nullptr, (float*)p_Wc,
                                 832, 128, 128, 128, 128);
    }
    // pq = x @ [Wd|Ws]      [N,64] @ [64,128]
    {
        dim3 g((Nn + 127) / 128, 1);
        sgemm_kernel<<<g, 256>>>(x, (const float*)p_Wds, nullptr, (float*)p_pq,
                                 Nn, 64, 64, 128, 128);
    }
    count_kernel<<<(E + 255) / 256, 256>>>(ei, E);
    scan_kernel<<<1, 1024>>>(Nn);
    scatter_kernel<<<(E + 255) / 256, 256>>>(ei, ea, E);
    agg_kernel<<<(Nn + 3) / 4, 256>>>(Nn);
    pool_feat_kernel<<<GNUM * 4, 256>>>(batch, x, Nn);
    zsmall_kernel<<<GNUM, 128>>>();
    mlp_kernel<<<1, 1024>>>(g1, be1, W2, b2, g2, be2, Wr1, br1, gr1, ber1,
                            Wr2, br2, gr2, ber2, Wout, bout, out);
}

// round 13
// speedup vs baseline: 2.9031x; 1.5717x over previous
#include <cuda_runtime.h>
#include <math.h>

// Problem constants (shapes fixed by dataset)
#define NMAX 50000
#define EMAX 800000
#define GNUM 64
// F=64, HG=HL=128; virtual feat width = 64 + 12*64 = 832

// ---------------- scratch (__device__ globals; no allocation allowed) ----------
__device__ float    d_pq[NMAX * 128];          // [p | q] per node
__device__ int      d_deg[NMAX];
__device__ int      d_off[NMAX];
__device__ int      d_fill[NMAX];
__device__ int2     d_edgeS[EMAX];             // (src, ea-bits) reordered by dst-CSR
__device__ int      d_bsum[1024];
__device__ int      d_bbase[1024];
__device__ float    d_fsum[GNUM * 832];        // per-graph summed virtual feat
__device__ float    d_z[GNUM * 128];           // z = featbar @ Wc + bc (pre-BN)
__device__ float    d_Wds[64 * 128];           // [Wd | Ws]
__device__ float    d_Wc[832 * 128];           // W_post @ W_lin
__device__ float    d_bc[128];                 // b_post @ W_lin + b_lin
__device__ float    d_v[64];                   // W_edge @ W_pre_e
__device__ float    d_cvec[64];                // b_edge @ W_pre_e + b_pre

// ------------------------- f32x2 packed helpers --------------------------------
__device__ __forceinline__ unsigned long long dup2(float x) {
    unsigned long long r;
    asm("mov.b64 %0, {%1, %1};" : "=l"(r) : "f"(x));
    return r;
}
__device__ __forceinline__ unsigned long long fma2(unsigned long long a,
                                                   unsigned long long b,
                                                   unsigned long long c) {
    unsigned long long d;
    asm("fma.rn.f32x2 %0, %1, %2, %3;" : "=l"(d) : "l"(a), "l"(b), "l"(c));
    return d;
}
__device__ __forceinline__ void unpack2(unsigned long long u, float& lo, float& hi) {
    asm("mov.b64 {%0, %1}, %2;" : "=f"(lo), "=f"(hi) : "l"(u));
}
__device__ __forceinline__ void cpasync16(unsigned dst, const void* src) {
    asm volatile("cp.async.ca.shared.global [%0], [%1], 16;" :: "r"(dst), "l"(src));
}

// ------------------------------- init ------------------------------------------
__global__ void init_kernel(int Nn) {
    int i = blockIdx.x * blockDim.x + threadIdx.x;
    if (i < Nn) d_deg[i] = 0;
    if (i < GNUM * 832) d_fsum[i] = 0.f;
}

// --------------------------- tiny precomputes ----------------------------------
__global__ void prep_kernel(const float* __restrict__ W_edge, const float* __restrict__ b_edge,
                            const float* __restrict__ W_pre,  const float* __restrict__ b_pre,
                            const float* __restrict__ b_post, const float* __restrict__ W_lin,
                            const float* __restrict__ b_lin) {
    int i = blockIdx.x * blockDim.x + threadIdx.x;
    if (i < 64 * 128) {
        int k = i >> 7, j = i & 127;
        d_Wds[i] = (j < 64) ? W_pre[k * 64 + j] : W_pre[(64 + k) * 64 + (j - 64)];
    } else if (i < 64 * 128 + 128) {
        int j = i - 64 * 128;
        float acc = b_lin[j];
        for (int k = 0; k < 128; k++) acc = fmaf(b_post[k], W_lin[k * 128 + j], acc);
        d_bc[j] = acc;
    } else if (i < 64 * 128 + 128 + 64) {
        int j = i - (64 * 128 + 128);
        float av = 0.f, ac = 0.f;
        for (int k = 0; k < 64; k++) {
            float w = W_pre[(128 + k) * 64 + j];
            av = fmaf(W_edge[k], w, av);
            ac = fmaf(b_edge[k], w, ac);
        }
        d_v[j]    = av;
        d_cvec[j] = ac + b_pre[j];
    }
}

// ------------- fp32x2 GEMM: BM=128, BN=128, BK=16, 256 thr, 8x8 ----------------
__global__ __launch_bounds__(256, 2) void sgemm_kernel(
    const float* __restrict__ A, const float* __restrict__ B,
    const float* __restrict__ bias, float* __restrict__ C,
    int M, int K, int lda, int ldb, int ldc) {
    __shared__ __align__(16) float As[2][128][20];
    __shared__ __align__(16) float Bs[2][16][132];

    const int tid  = threadIdx.x;
    const int row0 = blockIdx.x * 128;
    const int col0 = blockIdx.y * 128;
    const int tr   = (tid >> 4) << 3;
    const int tc   = (tid & 15) << 3;

    const unsigned sA = (unsigned)__cvta_generic_to_shared(&As[0][0][0]);
    const unsigned sB = (unsigned)__cvta_generic_to_shared(&Bs[0][0][0]);

    unsigned long long acc2[8][4];
#pragma unroll
    for (int i = 0; i < 8; i++)
#pragma unroll
        for (int p = 0; p < 4; p++) acc2[i][p] = 0ull;

    auto issue = [&](int kt, int buf) {
        int k0 = kt << 4;
#pragma unroll
        for (int t = 0; t < 2; t++) {
            int c  = tid + t * 256;
            int m  = c >> 2, kq = (c & 3) << 2;
            if (row0 + m < M)
                cpasync16(sA + (unsigned)(buf * 2560 + m * 20 + kq) * 4,
                          A + (size_t)(row0 + m) * lda + k0 + kq);
            int kr = c >> 5, n4 = (c & 31) << 2;
            cpasync16(sB + (unsigned)(buf * 2112 + kr * 132 + n4) * 4,
                      B + (size_t)(k0 + kr) * ldb + col0 + n4);
        }
        asm volatile("cp.async.commit_group;");
    };

    const int KT = K >> 4;
    issue(0, 0);

    int buf = 0;
    for (int kt = 0; kt < KT; kt++) {
        if (kt + 1 < KT) {
            issue(kt + 1, buf ^ 1);
            asm volatile("cp.async.wait_group 1;");
        } else {
            asm volatile("cp.async.wait_group 0;");
        }
        __syncthreads();

#pragma unroll
        for (int kk4 = 0; kk4 < 4; kk4++) {
            float4 a4[8];
#pragma unroll
            for (int i = 0; i < 8; i++)
                a4[i] = *reinterpret_cast<const float4*>(&As[buf][tr + i][kk4 << 2]);
#pragma unroll
            for (int kkl = 0; kkl < 4; kkl++) {
                int kk = (kk4 << 2) + kkl;
                ulonglong2 b0 = *reinterpret_cast<const ulonglong2*>(&Bs[buf][kk][tc]);
                ulonglong2 b1 = *reinterpret_cast<const ulonglong2*>(&Bs[buf][kk][tc + 4]);
                unsigned long long bv[4] = {b0.x, b0.y, b1.x, b1.y};
#pragma unroll
                for (int i = 0; i < 8; i++) {
                    float av = reinterpret_cast<const float*>(&a4[i])[kkl];
                    unsigned long long aa = dup2(av);
#pragma unroll
                    for (int p = 0; p < 4; p++) acc2[i][p] = fma2(aa, bv[p], acc2[i][p]);
                }
            }
        }
        __syncthreads();
        buf ^= 1;
    }

#pragma unroll
    for (int i = 0; i < 8; i++) {
        int gr = row0 + tr + i;
        if (gr >= M) continue;
        float cv[8];
#pragma unroll
        for (int p = 0; p < 4; p++) unpack2(acc2[i][p], cv[2 * p], cv[2 * p + 1]);
        if (bias) {
#pragma unroll
            for (int q = 0; q < 8; q++) cv[q] += bias[col0 + tc + q];
        }
        float* Cp = C + (size_t)gr * ldc + col0 + tc;
        *reinterpret_cast<float4*>(Cp)     = make_float4(cv[0], cv[1], cv[2], cv[3]);
        *reinterpret_cast<float4*>(Cp + 4) = make_float4(cv[4], cv[5], cv[6], cv[7]);
    }
}

// ------------------------------- CSR build -------------------------------------
__global__ void count_kernel(const int* __restrict__ ei, int E) {
    int e = blockIdx.x * blockDim.x + threadIdx.x;
    if (e >= E) return;
    atomicAdd(&d_deg[ei[E + e]], 1);
}

// Multi-block coalesced scan: A) block sums, B) scan of block sums, C) offsets.
__global__ void scanA_kernel(int Nn) {
    __shared__ int sh[256];
    int t = threadIdx.x;
    int i = blockIdx.x * 256 + t;
    int v = (i < Nn) ? d_deg[i] : 0;
    sh[t] = v;
    __syncthreads();
    for (int s = 128; s > 0; s >>= 1) {
        if (t < s) sh[t] += sh[t + s];
        __syncthreads();
    }
    if (t == 0) d_bsum[blockIdx.x] = sh[0];
}

__global__ void scanB_kernel(int nb) {
    __shared__ int sh[1024];
    int t = threadIdx.x;
    int v = (t < nb) ? d_bsum[t] : 0;
    sh[t] = v;
    __syncthreads();
    for (int d = 1; d < 1024; d <<= 1) {
        int u = (t >= d) ? sh[t - d] : 0;
        __syncthreads();
        sh[t] += u;
        __syncthreads();
    }
    if (t < nb) d_bbase[t] = sh[t] - v;   // exclusive base
}

__global__ void scanC_kernel(int Nn) {
    __shared__ int sh[256];
    int t = threadIdx.x;
    int i = blockIdx.x * 256 + t;
    int v = (i < Nn) ? d_deg[i] : 0;
    sh[t] = v;
    __syncthreads();
    for (int d = 1; d < 256; d <<= 1) {
        int u = (t >= d) ? sh[t - d] : 0;
        __syncthreads();
        sh[t] += u;
        __syncthreads();
    }
    int excl = sh[t] - v + d_bbase[blockIdx.x];
    if (i < Nn) {
        d_off[i]  = excl;
        d_fill[i] = excl;
    }
}

__global__ void scatter_kernel(const int* __restrict__ ei, const float* __restrict__ ea, int E) {
    int e = blockIdx.x * blockDim.x + threadIdx.x;
    if (e >= E) return;
    int d = ei[E + e];
    int pos = atomicAdd(&d_fill[d], 1);
    d_edgeS[pos] = make_int2(ei[e], __float_as_int(ea[e]));
}

// ------ fused per-node aggregation + graph pooling (register accumulation) -----
// 256 threads = 4 node-lanes x 64 feature-threads; 32 nodes per block.
// Fast path (whole block in one graph): accumulate 13 pooled sums in registers,
// reduce across lanes in smem, one atomicAdd set per block.
__global__ __launch_bounds__(256) void agg_kernel(const int* __restrict__ batch,
                                                  const float* __restrict__ x, int Nn) {
    int tid  = threadIdx.x;
    int lane = tid >> 6;
    int f    = tid & 63;
    int n0   = blockIdx.x * 32;

    bool fast = (n0 + 31 < Nn) && (batch[n0] == batch[n0 + 31]);
    int gfast = batch[n0];

    float vf = d_v[f];
    float cf = d_cvec[f];

    float A[13];
#pragma unroll
    for (int c = 0; c < 13; c++) A[c] = 0.f;

#pragma unroll 1
    for (int i = 0; i < 8; i++) {
        int n = n0 + i * 4 + lane;
        if (n >= Nn) continue;

        int off = d_off[n];
        int deg = d_deg[n];
        float pdf = d_pq[n * 128 + f];
        float xv  = x[n * 64 + f];

        float sum = 0.f, sq = 0.f;
        float mn = INFINITY, mx = -INFINITY;
        int jj = 0;
        for (; jj + 4 <= deg; jj += 4) {
            int2 e0 = d_edgeS[off + jj];
            int2 e1 = d_edgeS[off + jj + 1];
            int2 e2 = d_edgeS[off + jj + 2];
            int2 e3 = d_edgeS[off + jj + 3];
            float q0 = d_pq[e0.x * 128 + 64 + f];
            float q1 = d_pq[e1.x * 128 + 64 + f];
            float q2 = d_pq[e2.x * 128 + 64 + f];
            float q3 = d_pq[e3.x * 128 + 64 + f];
            float m0 = pdf + q0 + __int_as_float(e0.y) * vf + cf;
            float m1 = pdf + q1 + __int_as_float(e1.y) * vf + cf;
            float m2 = pdf + q2 + __int_as_float(e2.y) * vf + cf;
            float m3 = pdf + q3 + __int_as_float(e3.y) * vf + cf;
            sum += m0; sq = fmaf(m0, m0, sq); mn = fminf(mn, m0); mx = fmaxf(mx, m0);
            sum += m1; sq = fmaf(m1, m1, sq); mn = fminf(mn, m1); mx = fmaxf(mx, m1);
            sum += m2; sq = fmaf(m2, m2, sq); mn = fminf(mn, m2); mx = fmaxf(mx, m2);
            sum += m3; sq = fmaf(m3, m3, sq); mn = fminf(mn, m3); mx = fmaxf(mx, m3);
        }
        for (; jj < deg; jj++) {
            int2 ee = d_edgeS[off + jj];
            float m = pdf + d_pq[ee.x * 128 + 64 + f] + __int_as_float(ee.y) * vf + cf;
            sum += m; sq = fmaf(m, m, sq); mn = fminf(mn, m); mx = fmaxf(mx, m);
        }

        float cnt1  = fmaxf((float)deg, 1.f);
        float inv   = 1.f / cnt1;
        float mean  = sum * inv;
        float mean2 = sq * inv;
        float var   = mean2 - mean * mean;
        float sd    = sqrtf(fmaxf(var, 0.f) + 1e-5f);
        float vmn   = (deg > 0) ? mn : 0.f;
        float vmx   = (deg > 0) ? mx : 0.f;
        float amp   = logf(cnt1 + 1.f) * (1.0f / 2.19722457733621938f);  // / log(9)
        float iamp  = 1.f / amp;

        if (fast) {
            A[0]  += xv;
            A[1]  += mean;        A[2]  += vmn;        A[3]  += vmx;        A[4]  += sd;
            A[5]  += mean * amp;  A[6]  += vmn * amp;  A[7]  += vmx * amp;  A[8]  += sd * amp;
            A[9]  += mean * iamp; A[10] += vmn * iamp; A[11] += vmx * iamp; A[12] += sd * iamp;
        } else {
            float* F = d_fsum + batch[n] * 832;
            atomicAdd(&F[f],        xv);
            atomicAdd(&F[64  + f],  mean);        atomicAdd(&F[128 + f], vmn);
            atomicAdd(&F[192 + f],  vmx);         atomicAdd(&F[256 + f], sd);
            atomicAdd(&F[320 + f],  mean * amp);  atomicAdd(&F[384 + f], vmn * amp);
            atomicAdd(&F[448 + f],  vmx * amp);   atomicAdd(&F[512 + f], sd * amp);
            atomicAdd(&F[576 + f],  mean * iamp); atomicAdd(&F[640 + f], vmn * iamp);
            atomicAdd(&F[704 + f],  vmx * iamp);  atomicAdd(&F[768 + f], sd * iamp);
        }
    }

    if (fast) {
        __shared__ float S[256];
        float* F = d_fsum + gfast * 832;
#pragma unroll
        for (int c = 0; c < 13; c++) {
            S[tid] = A[c];
            __syncthreads();
            if (lane == 0)
                atomicAdd(&F[c * 64 + f], S[f] + S[64 + f] + S[128 + f] + S[192 + f]);
            __syncthreads();
        }
    }
}

// ------------- z = (fsum/cnt) @ Wc + bc   [64,832]@[832,128] -------------------
__global__ __launch_bounds__(128) void zsmall_kernel(const int* __restrict__ batch, int Nn) {
    int g = blockIdx.x;
    int j = threadIdx.x;
    int lo = 0, hi = Nn;
    while (lo < hi) { int m = (lo + hi) >> 1; if (batch[m] < g) lo = m + 1; else hi = m; }
    int lo2 = lo, hi2 = Nn;
    while (lo2 < hi2) { int m = (lo2 + hi2) >> 1; if (batch[m] < g + 1) lo2 = m + 1; else hi2 = m; }
    float inv = 1.f / fmaxf((float)(lo2 - lo), 1.f);
    const float* F = d_fsum + g * 832;
    float acc = d_bc[j];
    for (int k = 0; k < 832; k++)
        acc = fmaf(F[k] * inv, d_Wc[k * 128 + j], acc);
    d_z[g * 128 + j] = acc;
}

// ------------------------------- MLP head --------------------------------------
__device__ __forceinline__ void mlp_stats(float ps, float pq2, int rr, int j,
                                          float* redS, float* redQ,
                                          float* sgS, float* sbS,
                                          const float* __restrict__ g,
                                          const float* __restrict__ be) {
    redS[rr * 128 + j] = ps;
    redQ[rr * 128 + j] = pq2;
    __syncthreads();
    if (rr == 0) {
        float s = 0.f, q = 0.f;
#pragma unroll
        for (int r = 0; r < 8; r++) { s += redS[r * 128 + j]; q += redQ[r * 128 + j]; }
        float mu  = s * (1.f / 64.f);
        float var = q * (1.f / 64.f) - mu * mu;
        float is  = rsqrtf(fmaxf(var, 0.f) + 1e-5f);
        float sg  = g[j] * is;
        sgS[j] = sg;
        sbS[j] = be[j] - mu * sg;
    }
    __syncthreads();
}

__device__ __forceinline__ void mlp_layer(float* zS, float* redS, float* redQ,
                                          float* sgS, float* sbS,
                                          const float* __restrict__ W, const float* __restrict__ b,
                                          const float* __restrict__ g, const float* __restrict__ be,
                                          int rr, int j, float* rsave, const float* radd) {
    float acc[8];
#pragma unroll
    for (int u = 0; u < 8; u++) {
        int i = rr + u * 8;
        float a = b[j];
        for (int k = 0; k < 128; k++) a = fmaf(zS[i * 128 + k], W[k * 128 + j], a);
        acc[u] = a;
    }
    float ps = 0.f, pq2 = 0.f;
#pragma unroll
    for (int u = 0; u < 8; u++) { ps += acc[u]; pq2 = fmaf(acc[u], acc[u], pq2); }
    mlp_stats(ps, pq2, rr, j, redS, redQ, sgS, sbS, g, be);
#pragma unroll
    for (int u = 0; u < 8; u++) {
        float val = acc[u] * sgS[j] + sbS[j];
        if (radd) val += radd[u];
        val = fmaxf(val, 0.f);
        zS[(rr + u * 8) * 128 + j] = val;
        if (rsave) rsave[u] = val;
    }
    __syncthreads();
}

__global__ __launch_bounds__(1024) void mlp_kernel(
        const float* __restrict__ g1,  const float* __restrict__ be1,
        const float* __restrict__ W2,  const float* __restrict__ b2,
        const float* __restrict__ g2,  const float* __restrict__ be2,
        const float* __restrict__ Wr1, const float* __restrict__ br1,
        const float* __restrict__ gr1, const float* __restrict__ ber1,
        const float* __restrict__ Wr2, const float* __restrict__ br2,
        const float* __restrict__ gr2, const float* __restrict__ ber2,
        const float* __restrict__ Wout, const float* __restrict__ bout,
        float* __restrict__ out) {
    __shared__ float zS[64 * 128];
    __shared__ float redS[8 * 128];
    __shared__ float redQ[8 * 128];
    __shared__ float sgS[128], sbS[128];
    int tid = threadIdx.x;
    int rr = tid >> 7, j = tid & 127;

    float v8[8];
#pragma unroll
    for (int u = 0; u < 8; u++) {
        int i = rr + u * 8;
        v8[u] = d_z[i * 128 + j];
    }
    {
        float ps = 0.f, pq2 = 0.f;
#pragma unroll
        for (int u = 0; u < 8; u++) { ps += v8[u]; pq2 = fmaf(v8[u], v8[u], pq2); }
        mlp_stats(ps, pq2, rr, j, redS, redQ, sgS, sbS, g1, be1);
#pragma unroll
        for (int u = 0; u < 8; u++)
            zS[(rr + u * 8) * 128 + j] = fmaxf(v8[u] * sgS[j] + sbS[j], 0.f);
        __syncthreads();
    }

    float res[8];
    mlp_layer(zS, redS, redQ, sgS, sbS, W2,  b2,  g2,  be2,  rr, j, res,    nullptr);
    mlp_layer(zS, redS, redQ, sgS, sbS, Wr1, br1, gr1, ber1, rr, j, nullptr, nullptr);
    mlp_layer(zS, redS, redQ, sgS, sbS, Wr2, br2, gr2, ber2, rr, j, nullptr, res);

    if (tid < 64) {
        float a = bout[0];
        for (int k = 0; k < 128; k++) a = fmaf(zS[tid * 128 + k], Wout[k], a);
        out[tid] = a;
    }
}

// --------------------------------- launch --------------------------------------
extern "C" void kernel_launch(void* const* d_in, const int* in_sizes, int n_in,
                              void* d_out, int out_size) {
    const float* x      = (const float*)d_in[0];
    const int*   ei     = (const int*)d_in[1];
    const float* ea     = (const float*)d_in[2];
    const int*   batch  = (const int*)d_in[3];
    const float* W_edge = (const float*)d_in[4];
    const float* b_edge = (const float*)d_in[5];
    const float* W_pre  = (const float*)d_in[6];
    const float* b_pre  = (const float*)d_in[7];
    const float* W_post = (const float*)d_in[8];
    const float* b_post = (const float*)d_in[9];
    const float* W_lin  = (const float*)d_in[10];
    const float* b_lin  = (const float*)d_in[11];
    const float* g1  = (const float*)d_in[12];
    const float* be1 = (const float*)d_in[13];
    const float* W2  = (const float*)d_in[14];
    const float* b2  = (const float*)d_in[15];
    const float* g2  = (const float*)d_in[16];
    const float* be2 = (const float*)d_in[17];
    const float* Wr1 = (const float*)d_in[18];
    const float* br1 = (const float*)d_in[19];
    const float* gr1 = (const float*)d_in[20];
    const float* ber1= (const float*)d_in[21];
    const float* Wr2 = (const float*)d_in[22];
    const float* br2 = (const float*)d_in[23];
    const float* gr2 = (const float*)d_in[24];
    const float* ber2= (const float*)d_in[25];
    const float* Wout= (const float*)d_in[26];
    const float* bout= (const float*)d_in[27];
    float* out = (float*)d_out;

    const int Nn = in_sizes[0] / 64;
    const int E  = in_sizes[2];
    const int NB = (Nn + 255) / 256;

    void *p_pq, *p_Wds, *p_Wc;
    cudaGetSymbolAddress(&p_pq,  d_pq);
    cudaGetSymbolAddress(&p_Wds, d_Wds);
    cudaGetSymbolAddress(&p_Wc,  d_Wc);

    init_kernel<<<(GNUM * 832 + 255) / 256, 256>>>(Nn);
    prep_kernel<<<(64 * 128 + 128 + 64 + 255) / 256, 256>>>(W_edge, b_edge, W_pre, b_pre,
                                                            b_post, W_lin, b_lin);
    // Wc = W_post @ W_lin   [832,128] @ [128,128]
    {
        dim3 g((832 + 127) / 128, 1);
        sgemm_kernel<<<g, 256>>>(W_post, W_lin, nullptr, (float*)p_Wc,
                                 832, 128, 128, 128, 128);
    }
    // pq = x @ [Wd|Ws]      [N,64] @ [64,128]
    {
        dim3 g((Nn + 127) / 128, 1);
        sgemm_kernel<<<g, 256>>>(x, (const float*)p_Wds, nullptr, (float*)p_pq,
                                 Nn, 64, 64, 128, 128);
    }
    count_kernel<<<(E + 255) / 256, 256>>>(ei, E);
    scanA_kernel<<<NB, 256>>>(Nn);
    scanB_kernel<<<1, 1024>>>(NB);
    scanC_kernel<<<NB, 256>>>(Nn);
    scatter_kernel<<<(E + 255) / 256, 256>>>(ei, ea, E);
    agg_kernel<<<(Nn + 31) / 32, 256>>>(batch, x, Nn);
    zsmall_kernel<<<GNUM, 128>>>(batch, Nn);
    mlp_kernel<<<1, 1024>>>(g1, be1, W2, b2, g2, be2, Wr1, br1, gr1, ber1,
                            Wr2, br2, gr2, ber2, Wout, bout, out);
}

// round 14
// speedup vs baseline: 3.3263x; 1.1458x over previous
#include <cuda_runtime.h>
#include <math.h>

// Problem constants (shapes fixed by dataset)
#define NMAX 50000
#define EMAX 800000
#define GNUM 64
// F=64, HG=HL=128; virtual feat width = 64 + 12*64 = 832

// ---------------- scratch (__device__ globals; no allocation allowed) ----------
__device__ float    d_pq[NMAX * 128];          // [p | q] per node
__device__ int      d_deg[NMAX];
__device__ int      d_off[NMAX];
__device__ int      d_fill[NMAX];
__device__ int2     d_edgeS[EMAX];             // (src, ea-bits) reordered by dst-CSR
__device__ int      d_bsum[1024];
__device__ int      d_bbase[1024];
__device__ float    d_fsum[GNUM * 832];        // per-graph summed virtual feat
__device__ float    d_z[GNUM * 128];           // z = featbar @ Wc + bc (pre-BN)
__device__ float    d_Wds[64 * 128];           // [Wd | Ws]
__device__ float    d_Wc[832 * 128];           // W_post @ W_lin
__device__ float    d_bc[128];                 // b_post @ W_lin + b_lin
__device__ float    d_v[64];                   // W_edge @ W_pre_e
__device__ float    d_cvec[64];                // b_edge @ W_pre_e + b_pre

// ------------------------- f32x2 packed helpers --------------------------------
__device__ __forceinline__ unsigned long long dup2(float x) {
    unsigned long long r;
    asm("mov.b64 %0, {%1, %1};" : "=l"(r) : "f"(x));
    return r;
}
__device__ __forceinline__ unsigned long long fma2(unsigned long long a,
                                                   unsigned long long b,
                                                   unsigned long long c) {
    unsigned long long d;
    asm("fma.rn.f32x2 %0, %1, %2, %3;" : "=l"(d) : "l"(a), "l"(b), "l"(c));
    return d;
}
__device__ __forceinline__ void unpack2(unsigned long long u, float& lo, float& hi) {
    asm("mov.b64 {%0, %1}, %2;" : "=f"(lo), "=f"(hi) : "l"(u));
}
__device__ __forceinline__ void cpasync16(unsigned dst, const void* src) {
    asm volatile("cp.async.ca.shared.global [%0], [%1], 16;" :: "r"(dst), "l"(src));
}

// ------------------------------- init ------------------------------------------
__global__ void init_kernel(int Nn) {
    int i = blockIdx.x * blockDim.x + threadIdx.x;
    if (i < Nn) d_deg[i] = 0;
    if (i < GNUM * 832) d_fsum[i] = 0.f;
}

// --------------------------- tiny precomputes ----------------------------------
__global__ void prep_kernel(const float* __restrict__ W_edge, const float* __restrict__ b_edge,
                            const float* __restrict__ W_pre,  const float* __restrict__ b_pre,
                            const float* __restrict__ b_post, const float* __restrict__ W_lin,
                            const float* __restrict__ b_lin) {
    int i = blockIdx.x * blockDim.x + threadIdx.x;
    if (i < 64 * 128) {
        int k = i >> 7, j = i & 127;
        d_Wds[i] = (j < 64) ? W_pre[k * 64 + j] : W_pre[(64 + k) * 64 + (j - 64)];
    } else if (i < 64 * 128 + 128) {
        int j = i - 64 * 128;
        float acc = b_lin[j];
        for (int k = 0; k < 128; k++) acc = fmaf(b_post[k], W_lin[k * 128 + j], acc);
        d_bc[j] = acc;
    } else if (i < 64 * 128 + 128 + 64) {
        int j = i - (64 * 128 + 128);
        float av = 0.f, ac = 0.f;
        for (int k = 0; k < 64; k++) {
            float w = W_pre[(128 + k) * 64 + j];
            av = fmaf(W_edge[k], w, av);
            ac = fmaf(b_edge[k], w, ac);
        }
        d_v[j]    = av;
        d_cvec[j] = ac + b_pre[j];
    }
}

// ------------- fp32x2 GEMM: BM=128, BN=128, BK=16, 256 thr, 8x8 ----------------
__global__ __launch_bounds__(256, 2) void sgemm_kernel(
    const float* __restrict__ A, const float* __restrict__ B,
    const float* __restrict__ bias, float* __restrict__ C,
    int M, int K, int lda, int ldb, int ldc) {
    __shared__ __align__(16) float As[2][128][20];
    __shared__ __align__(16) float Bs[2][16][132];

    const int tid  = threadIdx.x;
    const int row0 = blockIdx.x * 128;
    const int col0 = blockIdx.y * 128;
    const int tr   = (tid >> 4) << 3;
    const int tc   = (tid & 15) << 3;

    const unsigned sA = (unsigned)__cvta_generic_to_shared(&As[0][0][0]);
    const unsigned sB = (unsigned)__cvta_generic_to_shared(&Bs[0][0][0]);

    unsigned long long acc2[8][4];
#pragma unroll
    for (int i = 0; i < 8; i++)
#pragma unroll
        for (int p = 0; p < 4; p++) acc2[i][p] = 0ull;

    auto issue = [&](int kt, int buf) {
        int k0 = kt << 4;
#pragma unroll
        for (int t = 0; t < 2; t++) {
            int c  = tid + t * 256;
            int m  = c >> 2, kq = (c & 3) << 2;
            if (row0 + m < M)
                cpasync16(sA + (unsigned)(buf * 2560 + m * 20 + kq) * 4,
                          A + (size_t)(row0 + m) * lda + k0 + kq);
            int kr = c >> 5, n4 = (c & 31) << 2;
            cpasync16(sB + (unsigned)(buf * 2112 + kr * 132 + n4) * 4,
                      B + (size_t)(k0 + kr) * ldb + col0 + n4);
        }
        asm volatile("cp.async.commit_group;");
    };

    const int KT = K >> 4;
    issue(0, 0);

    int buf = 0;
    for (int kt = 0; kt < KT; kt++) {
        if (kt + 1 < KT) {
            issue(kt + 1, buf ^ 1);
            asm volatile("cp.async.wait_group 1;");
        } else {
            asm volatile("cp.async.wait_group 0;");
        }
        __syncthreads();

#pragma unroll
        for (int kk4 = 0; kk4 < 4; kk4++) {
            float4 a4[8];
#pragma unroll
            for (int i = 0; i < 8; i++)
                a4[i] = *reinterpret_cast<const float4*>(&As[buf][tr + i][kk4 << 2]);
#pragma unroll
            for (int kkl = 0; kkl < 4; kkl++) {
                int kk = (kk4 << 2) + kkl;
                ulonglong2 b0 = *reinterpret_cast<const ulonglong2*>(&Bs[buf][kk][tc]);
                ulonglong2 b1 = *reinterpret_cast<const ulonglong2*>(&Bs[buf][kk][tc + 4]);
                unsigned long long bv[4] = {b0.x, b0.y, b1.x, b1.y};
#pragma unroll
                for (int i = 0; i < 8; i++) {
                    float av = reinterpret_cast<const float*>(&a4[i])[kkl];
                    unsigned long long aa = dup2(av);
#pragma unroll
                    for (int p = 0; p < 4; p++) acc2[i][p] = fma2(aa, bv[p], acc2[i][p]);
                }
            }
        }
        __syncthreads();
        buf ^= 1;
    }

#pragma unroll
    for (int i = 0; i < 8; i++) {
        int gr = row0 + tr + i;
        if (gr >= M) continue;
        float cv[8];
#pragma unroll
        for (int p = 0; p < 4; p++) unpack2(acc2[i][p], cv[2 * p], cv[2 * p + 1]);
        if (bias) {
#pragma unroll
            for (int q = 0; q < 8; q++) cv[q] += bias[col0 + tc + q];
        }
        float* Cp = C + (size_t)gr * ldc + col0 + tc;
        *reinterpret_cast<float4*>(Cp)     = make_float4(cv[0], cv[1], cv[2], cv[3]);
        *reinterpret_cast<float4*>(Cp + 4) = make_float4(cv[4], cv[5], cv[6], cv[7]);
    }
}

// ------------------------------- CSR build -------------------------------------
__global__ void count_kernel(const int* __restrict__ ei, int E) {
    int e = blockIdx.x * blockDim.x + threadIdx.x;
    if (e >= E) return;
    atomicAdd(&d_deg[ei[E + e]], 1);
}

__global__ void scanA_kernel(int Nn) {
    __shared__ int sh[256];
    int t = threadIdx.x;
    int i = blockIdx.x * 256 + t;
    int v = (i < Nn) ? d_deg[i] : 0;
    sh[t] = v;
    __syncthreads();
    for (int s = 128; s > 0; s >>= 1) {
        if (t < s) sh[t] += sh[t + s];
        __syncthreads();
    }
    if (t == 0) d_bsum[blockIdx.x] = sh[0];
}

__global__ void scanB_kernel(int nb) {
    __shared__ int sh[1024];
    int t = threadIdx.x;
    int v = (t < nb) ? d_bsum[t] : 0;
    sh[t] = v;
    __syncthreads();
    for (int d = 1; d < 1024; d <<= 1) {
        int u = (t >= d) ? sh[t - d] : 0;
        __syncthreads();
        sh[t] += u;
        __syncthreads();
    }
    if (t < nb) d_bbase[t] = sh[t] - v;   // exclusive base
}

__global__ void scanC_kernel(int Nn) {
    __shared__ int sh[256];
    int t = threadIdx.x;
    int i = blockIdx.x * 256 + t;
    int v = (i < Nn) ? d_deg[i] : 0;
    sh[t] = v;
    __syncthreads();
    for (int d = 1; d < 256; d <<= 1) {
        int u = (t >= d) ? sh[t - d] : 0;
        __syncthreads();
        sh[t] += u;
        __syncthreads();
    }
    int excl = sh[t] - v + d_bbase[blockIdx.x];
    if (i < Nn) {
        d_off[i]  = excl;
        d_fill[i] = excl;
    }
}

__global__ void scatter_kernel(const int* __restrict__ ei, const float* __restrict__ ea, int E) {
    int e = blockIdx.x * blockDim.x + threadIdx.x;
    if (e >= E) return;
    int d = ei[E + e];
    int pos = atomicAdd(&d_fill[d], 1);
    d_edgeS[pos] = make_int2(ei[e], __float_as_int(ea[e]));
}

// ------ fused per-node aggregation + graph pooling (register accumulation) -----
__global__ __launch_bounds__(256) void agg_kernel(const int* __restrict__ batch,
                                                  const float* __restrict__ x, int Nn) {
    int tid  = threadIdx.x;
    int lane = tid >> 6;
    int f    = tid & 63;
    int n0   = blockIdx.x * 32;

    bool fast = (n0 + 31 < Nn) && (batch[n0] == batch[n0 + 31]);
    int gfast = batch[n0];

    float vf = d_v[f];
    float cf = d_cvec[f];

    float A[13];
#pragma unroll
    for (int c = 0; c < 13; c++) A[c] = 0.f;

#pragma unroll 1
    for (int i = 0; i < 8; i++) {
        int n = n0 + i * 4 + lane;
        if (n >= Nn) continue;

        int off = d_off[n];
        int deg = d_deg[n];
        float pdf = d_pq[n * 128 + f];
        float xv  = x[n * 64 + f];

        float sum = 0.f, sq = 0.f;
        float mn = INFINITY, mx = -INFINITY;
        int jj = 0;
        for (; jj + 4 <= deg; jj += 4) {
            int2 e0 = d_edgeS[off + jj];
            int2 e1 = d_edgeS[off + jj + 1];
            int2 e2 = d_edgeS[off + jj + 2];
            int2 e3 = d_edgeS[off + jj + 3];
            float q0 = d_pq[e0.x * 128 + 64 + f];
            float q1 = d_pq[e1.x * 128 + 64 + f];
            float q2 = d_pq[e2.x * 128 + 64 + f];
            float q3 = d_pq[e3.x * 128 + 64 + f];
            float m0 = pdf + q0 + __int_as_float(e0.y) * vf + cf;
            float m1 = pdf + q1 + __int_as_float(e1.y) * vf + cf;
            float m2 = pdf + q2 + __int_as_float(e2.y) * vf + cf;
            float m3 = pdf + q3 + __int_as_float(e3.y) * vf + cf;
            sum += m0; sq = fmaf(m0, m0, sq); mn = fminf(mn, m0); mx = fmaxf(mx, m0);
            sum += m1; sq = fmaf(m1, m1, sq); mn = fminf(mn, m1); mx = fmaxf(mx, m1);
            sum += m2; sq = fmaf(m2, m2, sq); mn = fminf(mn, m2); mx = fmaxf(mx, m2);
            sum += m3; sq = fmaf(m3, m3, sq); mn = fminf(mn, m3); mx = fmaxf(mx, m3);
        }
        for (; jj < deg; jj++) {
            int2 ee = d_edgeS[off + jj];
            float m = pdf + d_pq[ee.x * 128 + 64 + f] + __int_as_float(ee.y) * vf + cf;
            sum += m; sq = fmaf(m, m, sq); mn = fminf(mn, m); mx = fmaxf(mx, m);
        }

        float cnt1  = fmaxf((float)deg, 1.f);
        float inv   = 1.f / cnt1;
        float mean  = sum * inv;
        float mean2 = sq * inv;
        float var   = mean2 - mean * mean;
        float sd    = sqrtf(fmaxf(var, 0.f) + 1e-5f);
        float vmn   = (deg > 0) ? mn : 0.f;
        float vmx   = (deg > 0) ? mx : 0.f;
        float amp   = logf(cnt1 + 1.f) * (1.0f / 2.19722457733621938f);  // / log(9)
        float iamp  = 1.f / amp;

        if (fast) {
            A[0]  += xv;
            A[1]  += mean;        A[2]  += vmn;        A[3]  += vmx;        A[4]  += sd;
            A[5]  += mean * amp;  A[6]  += vmn * amp;  A[7]  += vmx * amp;  A[8]  += sd * amp;
            A[9]  += mean * iamp; A[10] += vmn * iamp; A[11] += vmx * iamp; A[12] += sd * iamp;
        } else {
            float* F = d_fsum + batch[n] * 832;
            atomicAdd(&F[f],        xv);
            atomicAdd(&F[64  + f],  mean);        atomicAdd(&F[128 + f], vmn);
            atomicAdd(&F[192 + f],  vmx);         atomicAdd(&F[256 + f], sd);
            atomicAdd(&F[320 + f],  mean * amp);  atomicAdd(&F[384 + f], vmn * amp);
            atomicAdd(&F[448 + f],  vmx * amp);   atomicAdd(&F[512 + f], sd * amp);
            atomicAdd(&F[576 + f],  mean * iamp); atomicAdd(&F[640 + f], vmn * iamp);
            atomicAdd(&F[704 + f],  vmx * iamp);  atomicAdd(&F[768 + f], sd * iamp);
        }
    }

    if (fast) {
        __shared__ float S[256];
        float* F = d_fsum + gfast * 832;
#pragma unroll
        for (int c = 0; c < 13; c++) {
            S[tid] = A[c];
            __syncthreads();
            if (lane == 0)
                atomicAdd(&F[c * 64 + f], S[f] + S[64 + f] + S[128 + f] + S[192 + f]);
            __syncthreads();
        }
    }
}

// ------------- z = (fsum/cnt) @ Wc + bc   [64,832]@[832,128] -------------------
__global__ __launch_bounds__(128) void zsmall_kernel(const int* __restrict__ batch, int Nn) {
    int g = blockIdx.x;
    int j = threadIdx.x;
    int lo = 0, hi = Nn;
    while (lo < hi) { int m = (lo + hi) >> 1; if (batch[m] < g) lo = m + 1; else hi = m; }
    int lo2 = lo, hi2 = Nn;
    while (lo2 < hi2) { int m = (lo2 + hi2) >> 1; if (batch[m] < g + 1) lo2 = m + 1; else hi2 = m; }
    float inv = 1.f / fmaxf((float)(lo2 - lo), 1.f);
    const float* F = d_fsum + g * 832;
    float a0 = d_bc[j], a1 = 0.f, a2 = 0.f, a3 = 0.f;
#pragma unroll 4
    for (int k = 0; k < 832; k += 4) {
        a0 = fmaf(F[k]     * inv, d_Wc[(k)     * 128 + j], a0);
        a1 = fmaf(F[k + 1] * inv, d_Wc[(k + 1) * 128 + j], a1);
        a2 = fmaf(F[k + 2] * inv, d_Wc[(k + 2) * 128 + j], a2);
        a3 = fmaf(F[k + 3] * inv, d_Wc[(k + 3) * 128 + j], a3);
    }
    d_z[g * 128 + j] = (a0 + a1) + (a2 + a3);
}

// ------------------------------- MLP head --------------------------------------
// 1024 threads: rr = tid>>7 owns rows 8rr..8rr+7; j = tid&127 owns column j.
// Activations live transposed in smem: S[k*66 + i]  (k = column, i = row).
__device__ __forceinline__ void mlp_stats(float ps, float pq2, int rr, int j,
                                          float* redS, float* redQ,
                                          float* sgS, float* sbS,
                                          const float* __restrict__ g,
                                          const float* __restrict__ be) {
    redS[rr * 128 + j] = ps;
    redQ[rr * 128 + j] = pq2;
    __syncthreads();
    if (rr == 0) {
        float s = 0.f, q = 0.f;
#pragma unroll
        for (int r = 0; r < 8; r++) { s += redS[r * 128 + j]; q += redQ[r * 128 + j]; }
        float mu  = s * (1.f / 64.f);
        float var = q * (1.f / 64.f) - mu * mu;
        float is  = rsqrtf(fmaxf(var, 0.f) + 1e-5f);
        float sg  = g[j] * is;
        sgS[j] = sg;
        sbS[j] = be[j] - mu * sg;
    }
    __syncthreads();
}

__device__ __forceinline__ void mlp_layer(float* S, float* redS, float* redQ,
                                          float* sgS, float* sbS,
                                          const float* __restrict__ W, const float* __restrict__ b,
                                          const float* __restrict__ g, const float* __restrict__ be,
                                          int rr, int j, float* rsave, const float* radd) {
    const int i0 = rr * 8;
    unsigned long long acc2[4];
    unsigned long long binit = dup2(b[j]);
#pragma unroll
    for (int p = 0; p < 4; p++) acc2[p] = binit;

    for (int k = 0; k < 128; k++) {
        unsigned long long w2 = dup2(W[k * 128 + j]);
        const unsigned long long* Z =
            reinterpret_cast<const unsigned long long*>(&S[k * 66 + i0]);
#pragma unroll
        for (int p = 0; p < 4; p++) acc2[p] = fma2(Z[p], w2, acc2[p]);
    }

    float acc[8];
#pragma unroll
    for (int p = 0; p < 4; p++) unpack2(acc2[p], acc[2 * p], acc[2 * p + 1]);

    float ps = 0.f, pq2 = 0.f;
#pragma unroll
    for (int u = 0; u < 8; u++) { ps += acc[u]; pq2 = fmaf(acc[u], acc[u], pq2); }
    mlp_stats(ps, pq2, rr, j, redS, redQ, sgS, sbS, g, be);   // syncs cover S reads

    float sg = sgS[j], sb = sbS[j];
#pragma unroll
    for (int p = 0; p < 4; p++) {
        float v0 = acc[2 * p] * sg + sb;
        float v1 = acc[2 * p + 1] * sg + sb;
        if (radd) { v0 += radd[2 * p]; v1 += radd[2 * p + 1]; }
        v0 = fmaxf(v0, 0.f);
        v1 = fmaxf(v1, 0.f);
        *reinterpret_cast<float2*>(&S[j * 66 + i0 + 2 * p]) = make_float2(v0, v1);
        if (rsave) { rsave[2 * p] = v0; rsave[2 * p + 1] = v1; }
    }
    __syncthreads();
}

__global__ __launch_bounds__(1024) void mlp_kernel(
        const float* __restrict__ g1,  const float* __restrict__ be1,
        const float* __restrict__ W2,  const float* __restrict__ b2,
        const float* __restrict__ g2,  const float* __restrict__ be2,
        const float* __restrict__ Wr1, const float* __restrict__ br1,
        const float* __restrict__ gr1, const float* __restrict__ ber1,
        const float* __restrict__ Wr2, const float* __restrict__ br2,
        const float* __restrict__ gr2, const float* __restrict__ ber2,
        const float* __restrict__ Wout, const float* __restrict__ bout,
        float* __restrict__ out) {
    __shared__ float S[128 * 66];        // transposed activations, padded
    __shared__ float redS[8 * 128];
    __shared__ float redQ[8 * 128];
    __shared__ float sgS[128], sbS[128];
    int tid = threadIdx.x;
    int rr = tid >> 7, j = tid & 127;
    const int i0 = rr * 8;

    // load pooled pre-BN z for rows i0..i0+7, column j
    float v8[8];
#pragma unroll
    for (int u = 0; u < 8; u++) v8[u] = d_z[(i0 + u) * 128 + j];
    {
        float ps = 0.f, pq2 = 0.f;
#pragma unroll
        for (int u = 0; u < 8; u++) { ps += v8[u]; pq2 = fmaf(v8[u], v8[u], pq2); }
        mlp_stats(ps, pq2, rr, j, redS, redQ, sgS, sbS, g1, be1);
        float sg = sgS[j], sb = sbS[j];
#pragma unroll
        for (int p = 0; p < 4; p++) {
            float v0 = fmaxf(v8[2 * p] * sg + sb, 0.f);
            float v1 = fmaxf(v8[2 * p + 1] * sg + sb, 0.f);
            *reinterpret_cast<float2*>(&S[j * 66 + i0 + 2 * p]) = make_float2(v0, v1);
        }
        __syncthreads();
    }

    float res[8];
    mlp_layer(S, redS, redQ, sgS, sbS, W2,  b2,  g2,  be2,  rr, j, res,    nullptr);
    mlp_layer(S, redS, redQ, sgS, sbS, Wr1, br1, gr1, ber1, rr, j, nullptr, nullptr);
    mlp_layer(S, redS, redQ, sgS, sbS, Wr2, br2, gr2, ber2, rr, j, nullptr, res);

    if (tid < 64) {
        float a = bout[0];
        for (int k = 0; k < 128; k++) a = fmaf(S[k * 66 + tid], Wout[k], a);
        out[tid] = a;
    }
}

// --------------------------------- launch --------------------------------------
extern "C" void kernel_launch(void* const* d_in, const int* in_sizes, int n_in,
                              void* d_out, int out_size) {
    const float* x      = (const float*)d_in[0];
    const int*   ei     = (const int*)d_in[1];
    const float* ea     = (const float*)d_in[2];
    const int*   batch  = (const int*)d_in[3];
    const float* W_edge = (const float*)d_in[4];
    const float* b_edge = (const float*)d_in[5];
    const float* W_pre  = (const float*)d_in[6];
    const float* b_pre  = (const float*)d_in[7];
    const float* W_post = (const float*)d_in[8];
    const float* b_post = (const float*)d_in[9];
    const float* W_lin  = (const float*)d_in[10];
    const float* b_lin  = (const float*)d_in[11];
    const float* g1  = (const float*)d_in[12];
    const float* be1 = (const float*)d_in[13];
    const float* W2  = (const float*)d_in[14];
    const float* b2  = (const float*)d_in[15];
    const float* g2  = (const float*)d_in[16];
    const float* be2 = (const float*)d_in[17];
    const float* Wr1 = (const float*)d_in[18];
    const float* br1 = (const float*)d_in[19];
    const float* gr1 = (const float*)d_in[20];
    const float* ber1= (const float*)d_in[21];
    const float* Wr2 = (const float*)d_in[22];
    const float* br2 = (const float*)d_in[23];
    const float* gr2 = (const float*)d_in[24];
    const float* ber2= (const float*)d_in[25];
    const float* Wout= (const float*)d_in[26];
    const float* bout= (const float*)d_in[27];
    float* out = (float*)d_out;

    const int Nn = in_sizes[0] / 64;
    const int E  = in_sizes[2];
    const int NB = (Nn + 255) / 256;

    void *p_pq, *p_Wds, *p_Wc;
    cudaGetSymbolAddress(&p_pq,  d_pq);
    cudaGetSymbolAddress(&p_Wds, d_Wds);
    cudaGetSymbolAddress(&p_Wc,  d_Wc);

    // one-time stream/event resources (resource caching only; captured work is
    // identical on every call — record/wait are re-issued each launch)
    static cudaStream_t s_csr = nullptr;
    static cudaEvent_t  ev_fork = nullptr, ev_join = nullptr;
    if (!s_csr) {
        cudaStreamCreateWithFlags(&s_csr, cudaStreamNonBlocking);
        cudaEventCreateWithFlags(&ev_fork, cudaEventDisableTiming);
        cudaEventCreateWithFlags(&ev_join, cudaEventDisableTiming);
    }

    // fork: CSR chain on s_csr, GEMM chain on the launch stream
    cudaEventRecord(ev_fork, 0);
    cudaStreamWaitEvent(s_csr, ev_fork, 0);

    init_kernel<<<(GNUM * 832 + 255) / 256, 256, 0, s_csr>>>(Nn);
    count_kernel<<<(E + 255) / 256, 256, 0, s_csr>>>(ei, E);
    scanA_kernel<<<NB, 256, 0, s_csr>>>(Nn);
    scanB_kernel<<<1, 1024, 0, s_csr>>>(NB);
    scanC_kernel<<<NB, 256, 0, s_csr>>>(Nn);
    scatter_kernel<<<(E + 255) / 256, 256, 0, s_csr>>>(ei, ea, E);
    cudaEventRecord(ev_join, s_csr);

    prep_kernel<<<(64 * 128 + 128 + 64 + 255) / 256, 256>>>(W_edge, b_edge, W_pre, b_pre,
                                                            b_post, W_lin, b_lin);
    // pq = x @ [Wd|Ws]      [N,64] @ [64,128]
    {
        dim3 g((Nn + 127) / 128, 1);
        sgemm_kernel<<<g, 256>>>(x, (const float*)p_Wds, nullptr, (float*)p_pq,
                                 Nn, 64, 64, 128, 128);
    }
    // Wc = W_post @ W_lin   [832,128] @ [128,128]
    {
        dim3 g((832 + 127) / 128, 1);
        sgemm_kernel<<<g, 256>>>(W_post, W_lin, nullptr, (float*)p_Wc,
                                 832, 128, 128, 128, 128);
    }

    // join: aggregation needs CSR + init + pq + prep
    cudaStreamWaitEvent(0, ev_join, 0);
    agg_kernel<<<(Nn + 31) / 32, 256>>>(batch, x, Nn);
    zsmall_kernel<<<GNUM, 128>>>(batch, Nn);
    mlp_kernel<<<1, 1024>>>(g1, be1, W2, b2, g2, be2, Wr1, br1, gr1, ber1,
                            Wr2, br2, gr2, ber2, Wout, bout, out);
}

// round 15
// speedup vs baseline: 4.6071x; 1.3850x over previous
#include <cuda_runtime.h>
#include <math.h>

// Problem constants (shapes fixed by dataset)
#define NMAX 50000
#define EMAX 800000
#define GNUM 64
// F=64, HG=HL=128; virtual feat width = 64 + 12*64 = 832

// ---------------- scratch (__device__ globals; no allocation allowed) ----------
__device__ float    d_pq[NMAX * 128];          // [p | q] per node
__device__ int      d_deg[NMAX];
__device__ int      d_off[NMAX];
__device__ int      d_fill[NMAX];
__device__ int2     d_edgeS[EMAX];             // (src, ea-bits) reordered by dst-CSR
__device__ int      d_bsum[1024];
__device__ int      d_bbase[1024];
__device__ float    d_fsum[GNUM * 832];        // per-graph summed virtual feat
__device__ float    d_z[GNUM * 128];           // z = featbar @ Wc + bc (pre-BN)
__device__ float    d_Wds[64 * 128];           // [Wd | Ws]
__device__ float    d_Wc[832 * 128];           // W_post @ W_lin
__device__ float    d_bc[128];                 // b_post @ W_lin + b_lin
__device__ float    d_v[64];                   // W_edge @ W_pre_e
__device__ float    d_cvec[64];                // b_edge @ W_pre_e + b_pre

// ------------------------- f32x2 packed helpers --------------------------------
__device__ __forceinline__ unsigned long long dup2(float x) {
    unsigned long long r;
    asm("mov.b64 %0, {%1, %1};" : "=l"(r) : "f"(x));
    return r;
}
__device__ __forceinline__ unsigned long long fma2(unsigned long long a,
                                                   unsigned long long b,
                                                   unsigned long long c) {
    unsigned long long d;
    asm("fma.rn.f32x2 %0, %1, %2, %3;" : "=l"(d) : "l"(a), "l"(b), "l"(c));
    return d;
}
__device__ __forceinline__ void unpack2(unsigned long long u, float& lo, float& hi) {
    asm("mov.b64 {%0, %1}, %2;" : "=f"(lo), "=f"(hi) : "l"(u));
}
__device__ __forceinline__ void cpasync16(unsigned dst, const void* src) {
    asm volatile("cp.async.ca.shared.global [%0], [%1], 16;" :: "r"(dst), "l"(src));
}
__device__ __forceinline__ float4 mul4(float4 a, float s) {
    return make_float4(a.x * s, a.y * s, a.z * s, a.w * s);
}

// --------------------- deg zero (s_csr stream, before count) -------------------
__global__ void initdeg_kernel(int Nn) {
    int i = blockIdx.x * blockDim.x + threadIdx.x;
    if (i < Nn) d_deg[i] = 0;
}

// ---------------- precomputes + fsum zero (main stream) ------------------------
__global__ void prep_kernel(const float* __restrict__ W_edge, const float* __restrict__ b_edge,
                            const float* __restrict__ W_pre,  const float* __restrict__ b_pre,
                            const float* __restrict__ b_post, const float* __restrict__ W_lin,
                            const float* __restrict__ b_lin) {
    int i = blockIdx.x * blockDim.x + threadIdx.x;
    if (i < GNUM * 832) d_fsum[i] = 0.f;
    if (i < 64 * 128) {
        int k = i >> 7, j = i & 127;
        d_Wds[i] = (j < 64) ? W_pre[k * 64 + j] : W_pre[(64 + k) * 64 + (j - 64)];
    } else if (i < 64 * 128 + 128) {
        int j = i - 64 * 128;
        float acc = b_lin[j];
        for (int k = 0; k < 128; k++) acc = fmaf(b_post[k], W_lin[k * 128 + j], acc);
        d_bc[j] = acc;
    } else if (i < 64 * 128 + 128 + 64) {
        int j = i - (64 * 128 + 128);
        float av = 0.f, ac = 0.f;
        for (int k = 0; k < 64; k++) {
            float w = W_pre[(128 + k) * 64 + j];
            av = fmaf(W_edge[k], w, av);
            ac = fmaf(b_edge[k], w, ac);
        }
        d_v[j]    = av;
        d_cvec[j] = ac + b_pre[j];
    }
}

// ------------- fp32x2 GEMM: BM=128, BN=128, BK=16, 256 thr, 8x8 ----------------
__global__ __launch_bounds__(256, 2) void sgemm_kernel(
    const float* __restrict__ A, const float* __restrict__ B,
    const float* __restrict__ bias, float* __restrict__ C,
    int M, int K, int lda, int ldb, int ldc) {
    __shared__ __align__(16) float As[2][128][20];
    __shared__ __align__(16) float Bs[2][16][132];

    const int tid  = threadIdx.x;
    const int row0 = blockIdx.x * 128;
    const int col0 = blockIdx.y * 128;
    const int tr   = (tid >> 4) << 3;
    const int tc   = (tid & 15) << 3;

    const unsigned sA = (unsigned)__cvta_generic_to_shared(&As[0][0][0]);
    const unsigned sB = (unsigned)__cvta_generic_to_shared(&Bs[0][0][0]);

    unsigned long long acc2[8][4];
#pragma unroll
    for (int i = 0; i < 8; i++)
#pragma unroll
        for (int p = 0; p < 4; p++) acc2[i][p] = 0ull;

    auto issue = [&](int kt, int buf) {
        int k0 = kt << 4;
#pragma unroll
        for (int t = 0; t < 2; t++) {
            int c  = tid + t * 256;
            int m  = c >> 2, kq = (c & 3) << 2;
            if (row0 + m < M)
                cpasync16(sA + (unsigned)(buf * 2560 + m * 20 + kq) * 4,
                          A + (size_t)(row0 + m) * lda + k0 + kq);
            int kr = c >> 5, n4 = (c & 31) << 2;
            cpasync16(sB + (unsigned)(buf * 2112 + kr * 132 + n4) * 4,
                      B + (size_t)(k0 + kr) * ldb + col0 + n4);
        }
        asm volatile("cp.async.commit_group;");
    };

    const int KT = K >> 4;
    issue(0, 0);

    int buf = 0;
    for (int kt = 0; kt < KT; kt++) {
        if (kt + 1 < KT) {
            issue(kt + 1, buf ^ 1);
            asm volatile("cp.async.wait_group 1;");
        } else {
            asm volatile("cp.async.wait_group 0;");
        }
        __syncthreads();

#pragma unroll
        for (int kk4 = 0; kk4 < 4; kk4++) {
            float4 a4[8];
#pragma unroll
            for (int i = 0; i < 8; i++)
                a4[i] = *reinterpret_cast<const float4*>(&As[buf][tr + i][kk4 << 2]);
#pragma unroll
            for (int kkl = 0; kkl < 4; kkl++) {
                int kk = (kk4 << 2) + kkl;
                ulonglong2 b0 = *reinterpret_cast<const ulonglong2*>(&Bs[buf][kk][tc]);
                ulonglong2 b1 = *reinterpret_cast<const ulonglong2*>(&Bs[buf][kk][tc + 4]);
                unsigned long long bv[4] = {b0.x, b0.y, b1.x, b1.y};
#pragma unroll
                for (int i = 0; i < 8; i++) {
                    float av = reinterpret_cast<const float*>(&a4[i])[kkl];
                    unsigned long long aa = dup2(av);
#pragma unroll
                    for (int p = 0; p < 4; p++) acc2[i][p] = fma2(aa, bv[p], acc2[i][p]);
                }
            }
        }
        __syncthreads();
        buf ^= 1;
    }

#pragma unroll
    for (int i = 0; i < 8; i++) {
        int gr = row0 + tr + i;
        if (gr >= M) continue;
        float cv[8];
#pragma unroll
        for (int p = 0; p < 4; p++) unpack2(acc2[i][p], cv[2 * p], cv[2 * p + 1]);
        if (bias) {
#pragma unroll
            for (int q = 0; q < 8; q++) cv[q] += bias[col0 + tc + q];
        }
        float* Cp = C + (size_t)gr * ldc + col0 + tc;
        *reinterpret_cast<float4*>(Cp)     = make_float4(cv[0], cv[1], cv[2], cv[3]);
        *reinterpret_cast<float4*>(Cp + 4) = make_float4(cv[4], cv[5], cv[6], cv[7]);
    }
}

// ------------------------------- CSR build -------------------------------------
__global__ void count_kernel(const int* __restrict__ ei, int E) {
    int e = blockIdx.x * blockDim.x + threadIdx.x;
    if (e >= E) return;
    atomicAdd(&d_deg[ei[E + e]], 1);
}

__global__ void scanA_kernel(int Nn) {
    __shared__ int sh[256];
    int t = threadIdx.x;
    int i = blockIdx.x * 256 + t;
    int v = (i < Nn) ? d_deg[i] : 0;
    sh[t] = v;
    __syncthreads();
    for (int s = 128; s > 0; s >>= 1) {
        if (t < s) sh[t] += sh[t + s];
        __syncthreads();
    }
    if (t == 0) d_bsum[blockIdx.x] = sh[0];
}

__global__ void scanB_kernel(int nb) {
    __shared__ int sh[1024];
    int t = threadIdx.x;
    int v = (t < nb) ? d_bsum[t] : 0;
    sh[t] = v;
    __syncthreads();
    for (int d = 1; d < 1024; d <<= 1) {
        int u = (t >= d) ? sh[t - d] : 0;
        __syncthreads();
        sh[t] += u;
        __syncthreads();
    }
    if (t < nb) d_bbase[t] = sh[t] - v;   // exclusive base
}

__global__ void scanC_kernel(int Nn) {
    __shared__ int sh[256];
    int t = threadIdx.x;
    int i = blockIdx.x * 256 + t;
    int v = (i < Nn) ? d_deg[i] : 0;
    sh[t] = v;
    __syncthreads();
    for (int d = 1; d < 256; d <<= 1) {
        int u = (t >= d) ? sh[t - d] : 0;
        __syncthreads();
        sh[t] += u;
        __syncthreads();
    }
    int excl = sh[t] - v + d_bbase[blockIdx.x];
    if (i < Nn) {
        d_off[i]  = excl;
        d_fill[i] = excl;
    }
}

__global__ void scatter_kernel(const int* __restrict__ ei, const float* __restrict__ ea, int E) {
    int e = blockIdx.x * blockDim.x + threadIdx.x;
    if (e >= E) return;
    int d = ei[E + e];
    int pos = atomicAdd(&d_fill[d], 1);
    d_edgeS[pos] = make_int2(ei[e], __float_as_int(ea[e]));
}

// ------ fused per-node aggregation + graph pooling, float4 features ------------
// 256 threads = 16 node-lanes x 16 feature-threads (4 features each).
// Fast path (block's 16 nodes share one graph): smem-reduce 13 channels, one
// atomicAdd set per block. Edge records software-pipelined to hide edge->q chain.
#define AGG_ACC(EE, QQ)                                                         \
    do {                                                                        \
        float ea_ = __int_as_float((EE).y);                                     \
        float m0 = fmaf(ea_, vf.x, t.x) + (QQ).x;                               \
        float m1 = fmaf(ea_, vf.y, t.y) + (QQ).y;                               \
        float m2 = fmaf(ea_, vf.z, t.z) + (QQ).z;                               \
        float m3 = fmaf(ea_, vf.w, t.w) + (QQ).w;                               \
        sum.x += m0; sq.x = fmaf(m0, m0, sq.x); mn.x = fminf(mn.x, m0); mx.x = fmaxf(mx.x, m0); \
        sum.y += m1; sq.y = fmaf(m1, m1, sq.y); mn.y = fminf(mn.y, m1); mx.y = fmaxf(mx.y, m1); \
        sum.z += m2; sq.z = fmaf(m2, m2, sq.z); mn.z = fminf(mn.z, m2); mx.z = fmaxf(mx.z, m2); \
        sum.w += m3; sq.w = fmaf(m3, m3, sq.w); mn.w = fminf(mn.w, m3); mx.w = fmaxf(mx.w, m3); \
    } while (0)

__global__ __launch_bounds__(256) void agg_kernel(const int* __restrict__ batch,
                                                  const float* __restrict__ x, int Nn) {
    int tid  = threadIdx.x;
    int lane = tid >> 4;          // 0..15 node lane
    int ftid = tid & 15;
    int ft   = ftid << 2;         // feature base 0,4,..,60
    int n0   = blockIdx.x * 16;
    int n    = n0 + lane;
    bool valid = n < Nn;
    bool fast  = (n0 + 15 < Nn) && (batch[n0] == batch[n0 + 15]);

    float4 vf = *reinterpret_cast<const float4*>(&d_v[ft]);
    float4 cf = *reinterpret_cast<const float4*>(&d_cvec[ft]);

    float4 mean = make_float4(0, 0, 0, 0), vmn = mean, vmx = mean, sd = mean;
    float4 xv   = mean;
    float amp = 1.f, iamp = 1.f;

    if (valid) {
        int off = d_off[n];
        int deg = d_deg[n];
        float4 pdf = *reinterpret_cast<const float4*>(&d_pq[n * 128 + ft]);
        xv = *reinterpret_cast<const float4*>(&x[n * 64 + ft]);
        float4 t = make_float4(pdf.x + cf.x, pdf.y + cf.y, pdf.z + cf.z, pdf.w + cf.w);

        float4 sum = make_float4(0, 0, 0, 0), sq = sum;
        float4 mn = make_float4(INFINITY, INFINITY, INFINITY, INFINITY);
        float4 mx = make_float4(-INFINITY, -INFINITY, -INFINITY, -INFINITY);

        int jj = 0;
        if (deg >= 4) {
            int2 pe0 = d_edgeS[off + 0], pe1 = d_edgeS[off + 1];
            int2 pe2 = d_edgeS[off + 2], pe3 = d_edgeS[off + 3];
            for (; jj + 8 <= deg; jj += 4) {
                float4 q0 = *reinterpret_cast<const float4*>(&d_pq[pe0.x * 128 + 64 + ft]);
                float4 q1 = *reinterpret_cast<const float4*>(&d_pq[pe1.x * 128 + 64 + ft]);
                float4 q2 = *reinterpret_cast<const float4*>(&d_pq[pe2.x * 128 + 64 + ft]);
                float4 q3 = *reinterpret_cast<const float4*>(&d_pq[pe3.x * 128 + 64 + ft]);
                int2 ne0 = d_edgeS[off + jj + 4], ne1 = d_edgeS[off + jj + 5];
                int2 ne2 = d_edgeS[off + jj + 6], ne3 = d_edgeS[off + jj + 7];
                AGG_ACC(pe0, q0); AGG_ACC(pe1, q1); AGG_ACC(pe2, q2); AGG_ACC(pe3, q3);
                pe0 = ne0; pe1 = ne1; pe2 = ne2; pe3 = ne3;
            }
            {   // pending full group
                float4 q0 = *reinterpret_cast<const float4*>(&d_pq[pe0.x * 128 + 64 + ft]);
                float4 q1 = *reinterpret_cast<const float4*>(&d_pq[pe1.x * 128 + 64 + ft]);
                float4 q2 = *reinterpret_cast<const float4*>(&d_pq[pe2.x * 128 + 64 + ft]);
                float4 q3 = *reinterpret_cast<const float4*>(&d_pq[pe3.x * 128 + 64 + ft]);
                AGG_ACC(pe0, q0); AGG_ACC(pe1, q1); AGG_ACC(pe2, q2); AGG_ACC(pe3, q3);
                jj += 4;
            }
        }
        for (; jj < deg; jj++) {
            int2 ee = d_edgeS[off + jj];
            float4 qq = *reinterpret_cast<const float4*>(&d_pq[ee.x * 128 + 64 + ft]);
            AGG_ACC(ee, qq);
        }

        float cnt1 = fmaxf((float)deg, 1.f);
        float inv  = 1.f / cnt1;
        mean = mul4(sum, inv);
        float4 mean2 = mul4(sq, inv);
        sd.x = sqrtf(fmaxf(mean2.x - mean.x * mean.x, 0.f) + 1e-5f);
        sd.y = sqrtf(fmaxf(mean2.y - mean.y * mean.y, 0.f) + 1e-5f);
        sd.z = sqrtf(fmaxf(mean2.z - mean.z * mean.z, 0.f) + 1e-5f);
        sd.w = sqrtf(fmaxf(mean2.w - mean.w * mean.w, 0.f) + 1e-5f);
        bool has = deg > 0;
        vmn = has ? mn : make_float4(0, 0, 0, 0);
        vmx = has ? mx : make_float4(0, 0, 0, 0);
        amp  = logf(cnt1 + 1.f) * (1.0f / 2.19722457733621938f);   // / log(9)
        iamp = 1.f / amp;
    }

    if (fast) {
        __shared__ float S[16 * 64];   // [lane][feature]
        float* F = d_fsum + batch[n0] * 832;
#pragma unroll
        for (int c = 0; c < 13; c++) {
            float4 cv;
            if      (c == 0)  cv = xv;
            else if (c == 1)  cv = mean;
            else if (c == 2)  cv = vmn;
            else if (c == 3)  cv = vmx;
            else if (c == 4)  cv = sd;
            else if (c == 5)  cv = mul4(mean, amp);
            else if (c == 6)  cv = mul4(vmn, amp);
            else if (c == 7)  cv = mul4(vmx, amp);
            else if (c == 8)  cv = mul4(sd, amp);
            else if (c == 9)  cv = mul4(mean, iamp);
            else if (c == 10) cv = mul4(vmn, iamp);
            else if (c == 11) cv = mul4(vmx, iamp);
            else              cv = mul4(sd, iamp);
            *reinterpret_cast<float4*>(&S[lane * 64 + ft]) = cv;
            __syncthreads();
            if (tid < 64) {
                float s = 0.f;
#pragma unroll
                for (int l = 0; l < 16; l++) s += S[l * 64 + tid];
                atomicAdd(&F[c * 64 + tid], s);
            }
            __syncthreads();
        }
    } else if (valid) {
        float* F = d_fsum + batch[n] * 832;
        float4 ch[13];
        ch[0] = xv;  ch[1] = mean; ch[2] = vmn; ch[3] = vmx; ch[4] = sd;
        ch[5] = mul4(mean, amp);  ch[6]  = mul4(vmn, amp);  ch[7]  = mul4(vmx, amp);  ch[8]  = mul4(sd, amp);
        ch[9] = mul4(mean, iamp); ch[10] = mul4(vmn, iamp); ch[11] = mul4(vmx, iamp); ch[12] = mul4(sd, iamp);
#pragma unroll
        for (int c = 0; c < 13; c++) {
            atomicAdd(&F[c * 64 + ft + 0], ch[c].x);
            atomicAdd(&F[c * 64 + ft + 1], ch[c].y);
            atomicAdd(&F[c * 64 + ft + 2], ch[c].z);
            atomicAdd(&F[c * 64 + ft + 3], ch[c].w);
        }
    }
}

// ------------- z = (fsum/cnt) @ Wc + bc   [64,832]@[832,128] -------------------
// 512 threads: j = tid&127 (column), piece = tid>>7 (k-quarter of 208).
__global__ __launch_bounds__(512) void zsmall_kernel(const int* __restrict__ batch, int Nn) {
    __shared__ float Fs[832];
    __shared__ float red[512];
    int g = blockIdx.x;
    int tid = threadIdx.x;
    int j = tid & 127, piece = tid >> 7;

    int lo = 0, hi = Nn;
    while (lo < hi) { int m = (lo + hi) >> 1; if (batch[m] < g) lo = m + 1; else hi = m; }
    int lo2 = lo, hi2 = Nn;
    while (lo2 < hi2) { int m = (lo2 + hi2) >> 1; if (batch[m] < g + 1) lo2 = m + 1; else hi2 = m; }
    float inv = 1.f / fmaxf((float)(lo2 - lo), 1.f);

    for (int i = tid; i < 832; i += 512) Fs[i] = d_fsum[g * 832 + i] * inv;
    __syncthreads();

    int k0 = piece * 208;
    float a0 = (piece == 0) ? d_bc[j] : 0.f, a1 = 0.f, a2 = 0.f, a3 = 0.f;
#pragma unroll 4
    for (int k = 0; k < 208; k += 4) {
        a0 = fmaf(Fs[k0 + k],     d_Wc[(k0 + k)     * 128 + j], a0);
        a1 = fmaf(Fs[k0 + k + 1], d_Wc[(k0 + k + 1) * 128 + j], a1);
        a2 = fmaf(Fs[k0 + k + 2], d_Wc[(k0 + k + 2) * 128 + j], a2);
        a3 = fmaf(Fs[k0 + k + 3], d_Wc[(k0 + k + 3) * 128 + j], a3);
    }
    red[tid] = (a0 + a1) + (a2 + a3);
    __syncthreads();
    if (piece == 0)
        d_z[g * 128 + j] = (red[j] + red[128 + j]) + (red[256 + j] + red[384 + j]);
}

// ------------------------------- MLP head --------------------------------------
__device__ __forceinline__ void mlp_stats(float ps, float pq2, int rr, int j,
                                          float* redS, float* redQ,
                                          float* sgS, float* sbS,
                                          const float* __restrict__ g,
                                          const float* __restrict__ be) {
    redS[rr * 128 + j] = ps;
    redQ[rr * 128 + j] = pq2;
    __syncthreads();
    if (rr == 0) {
        float s = 0.f, q = 0.f;
#pragma unroll
        for (int r = 0; r < 8; r++) { s += redS[r * 128 + j]; q += redQ[r * 128 + j]; }
        float mu  = s * (1.f / 64.f);
        float var = q * (1.f / 64.f) - mu * mu;
        float is  = rsqrtf(fmaxf(var, 0.f) + 1e-5f);
        float sg  = g[j] * is;
        sgS[j] = sg;
        sbS[j] = be[j] - mu * sg;
    }
    __syncthreads();
}

__device__ __forceinline__ void mlp_layer(float* S, float* redS, float* redQ,
                                          float* sgS, float* sbS,
                                          const float* __restrict__ W, const float* __restrict__ b,
                                          const float* __restrict__ g, const float* __restrict__ be,
                                          int rr, int j, float* rsave, const float* radd) {
    const int i0 = rr * 8;
    unsigned long long acc2[4];
    unsigned long long binit = dup2(b[j]);
#pragma unroll
    for (int p = 0; p < 4; p++) acc2[p] = binit;

    for (int k = 0; k < 128; k++) {
        unsigned long long w2 = dup2(W[k * 128 + j]);
        const unsigned long long* Z =
            reinterpret_cast<const unsigned long long*>(&S[k * 66 + i0]);
#pragma unroll
        for (int p = 0; p < 4; p++) acc2[p] = fma2(Z[p], w2, acc2[p]);
    }

    float acc[8];
#pragma unroll
    for (int p = 0; p < 4; p++) unpack2(acc2[p], acc[2 * p], acc[2 * p + 1]);

    float ps = 0.f, pq2 = 0.f;
#pragma unroll
    for (int u = 0; u < 8; u++) { ps += acc[u]; pq2 = fmaf(acc[u], acc[u], pq2); }
    mlp_stats(ps, pq2, rr, j, redS, redQ, sgS, sbS, g, be);   // syncs cover S reads

    float sg = sgS[j], sb = sbS[j];
#pragma unroll
    for (int p = 0; p < 4; p++) {
        float v0 = acc[2 * p] * sg + sb;
        float v1 = acc[2 * p + 1] * sg + sb;
        if (radd) { v0 += radd[2 * p]; v1 += radd[2 * p + 1]; }
        v0 = fmaxf(v0, 0.f);
        v1 = fmaxf(v1, 0.f);
        *reinterpret_cast<float2*>(&S[j * 66 + i0 + 2 * p]) = make_float2(v0, v1);
        if (rsave) { rsave[2 * p] = v0; rsave[2 * p + 1] = v1; }
    }
    __syncthreads();
}

__global__ __launch_bounds__(1024) void mlp_kernel(
        const float* __restrict__ g1,  const float* __restrict__ be1,
        const float* __restrict__ W2,  const float* __restrict__ b2,
        const float* __restrict__ g2,  const float* __restrict__ be2,
        const float* __restrict__ Wr1, const float* __restrict__ br1,
        const float* __restrict__ gr1, const float* __restrict__ ber1,
        const float* __restrict__ Wr2, const float* __restrict__ br2,
        const float* __restrict__ gr2, const float* __restrict__ ber2,
        const float* __restrict__ Wout, const float* __restrict__ bout,
        float* __restrict__ out) {
    __shared__ float S[128 * 66];        // transposed activations, padded
    __shared__ float redS[8 * 128];
    __shared__ float redQ[8 * 128];
    __shared__ float sgS[128], sbS[128];
    int tid = threadIdx.x;
    int rr = tid >> 7, j = tid & 127;
    const int i0 = rr * 8;

    float v8[8];
#pragma unroll
    for (int u = 0; u < 8; u++) v8[u] = d_z[(i0 + u) * 128 + j];
    {
        float ps = 0.f, pq2 = 0.f;
#pragma unroll
        for (int u = 0; u < 8; u++) { ps += v8[u]; pq2 = fmaf(v8[u], v8[u], pq2); }
        mlp_stats(ps, pq2, rr, j, redS, redQ, sgS, sbS, g1, be1);
        float sg = sgS[j], sb = sbS[j];
#pragma unroll
        for (int p = 0; p < 4; p++) {
            float v0 = fmaxf(v8[2 * p] * sg + sb, 0.f);
            float v1 = fmaxf(v8[2 * p + 1] * sg + sb, 0.f);
            *reinterpret_cast<float2*>(&S[j * 66 + i0 + 2 * p]) = make_float2(v0, v1);
        }
        __syncthreads();
    }

    float res[8];
    mlp_layer(S, redS, redQ, sgS, sbS, W2,  b2,  g2,  be2,  rr, j, res,    nullptr);
    mlp_layer(S, redS, redQ, sgS, sbS, Wr1, br1, gr1, ber1, rr, j, nullptr, nullptr);
    mlp_layer(S, redS, redQ, sgS, sbS, Wr2, br2, gr2, ber2, rr, j, nullptr, res);

    if (tid < 64) {
        float a = bout[0];
        for (int k = 0; k < 128; k++) a = fmaf(S[k * 66 + tid], Wout[k], a);
        out[tid] = a;
    }
}

// --------------------------------- launch --------------------------------------
extern "C" void kernel_launch(void* const* d_in, const int* in_sizes, int n_in,
                              void* d_out, int out_size) {
    const float* x      = (const float*)d_in[0];
    const int*   ei     = (const int*)d_in[1];
    const float* ea     = (const float*)d_in[2];
    const int*   batch  = (const int*)d_in[3];
    const float* W_edge = (const float*)d_in[4];
    const float* b_edge = (const float*)d_in[5];
    const float* W_pre  = (const float*)d_in[6];
    const float* b_pre  = (const float*)d_in[7];
    const float* W_post = (const float*)d_in[8];
    const float* b_post = (const float*)d_in[9];
    const float* W_lin  = (const float*)d_in[10];
    const float* b_lin  = (const float*)d_in[11];
    const float* g1  = (const float*)d_in[12];
    const float* be1 = (const float*)d_in[13];
    const float* W2  = (const float*)d_in[14];
    const float* b2  = (const float*)d_in[15];
    const float* g2  = (const float*)d_in[16];
    const float* be2 = (const float*)d_in[17];
    const float* Wr1 = (const float*)d_in[18];
    const float* br1 = (const float*)d_in[19];
    const float* gr1 = (const float*)d_in[20];
    const float* ber1= (const float*)d_in[21];
    const float* Wr2 = (const float*)d_in[22];
    const float* br2 = (const float*)d_in[23];
    const float* gr2 = (const float*)d_in[24];
    const float* ber2= (const float*)d_in[25];
    const float* Wout= (const float*)d_in[26];
    const float* bout= (const float*)d_in[27];
    float* out = (float*)d_out;

    const int Nn = in_sizes[0] / 64;
    const int E  = in_sizes[2];
    const int NB = (Nn + 255) / 256;

    void *p_pq, *p_Wds, *p_Wc;
    cudaGetSymbolAddress(&p_pq,  d_pq);
    cudaGetSymbolAddress(&p_Wds, d_Wds);
    cudaGetSymbolAddress(&p_Wc,  d_Wc);

    // one-time stream/event resources (resource caching only; captured work is
    // identical on every call — record/wait are re-issued each launch)
    static cudaStream_t s_csr = nullptr;
    static cudaEvent_t  ev_fork = nullptr, ev_join = nullptr, ev_wc = nullptr;
    if (!s_csr) {
        cudaStreamCreateWithFlags(&s_csr, cudaStreamNonBlocking);
        cudaEventCreateWithFlags(&ev_fork, cudaEventDisableTiming);
        cudaEventCreateWithFlags(&ev_join, cudaEventDisableTiming);
        cudaEventCreateWithFlags(&ev_wc,   cudaEventDisableTiming);
    }

    // fork: CSR chain (+Wc) on s_csr, prep/pq on the launch stream
    cudaEventRecord(ev_fork, 0);
    cudaStreamWaitEvent(s_csr, ev_fork, 0);

    initdeg_kernel<<<NB, 256, 0, s_csr>>>(Nn);
    count_kernel<<<(E + 255) / 256, 256, 0, s_csr>>>(ei, E);
    scanA_kernel<<<NB, 256, 0, s_csr>>>(Nn);
    scanB_kernel<<<1, 1024, 0, s_csr>>>(NB);
    scanC_kernel<<<NB, 256, 0, s_csr>>>(Nn);
    scatter_kernel<<<(E + 255) / 256, 256, 0, s_csr>>>(ei, ea, E);
    cudaEventRecord(ev_join, s_csr);
    // Wc = W_post @ W_lin (only needed by zsmall) — overlaps agg on main stream
    {
        dim3 g((832 + 127) / 128, 1);
        sgemm_kernel<<<g, 256, 0, s_csr>>>(W_post, W_lin, nullptr, (float*)p_Wc,
                                           832, 128, 128, 128, 128);
    }
    cudaEventRecord(ev_wc, s_csr);

    prep_kernel<<<(GNUM * 832 + 255) / 256, 256>>>(W_edge, b_edge, W_pre, b_pre,
                                                   b_post, W_lin, b_lin);
    // pq = x @ [Wd|Ws]      [N,64] @ [64,128]
    {
        dim3 g((Nn + 127) / 128, 1);
        sgemm_kernel<<<g, 256>>>(x, (const float*)p_Wds, nullptr, (float*)p_pq,
                                 Nn, 64, 64, 128, 128);
    }

    // join: aggregation needs CSR + fsum-zero(prep) + pq + v/cvec(prep)
    cudaStreamWaitEvent(0, ev_join, 0);
    agg_kernel<<<(Nn + 15) / 16, 256>>>(batch, x, Nn);
    cudaStreamWaitEvent(0, ev_wc, 0);
    zsmall_kernel<<<GNUM, 512>>>(batch, Nn);
    mlp_kernel<<<1, 1024>>>(g1, be1, W2, b2, g2, be2, Wr1, br1, gr1, ber1,
                            Wr2, br2, gr2, ber2, Wout, bout, out);
}